// round 15
// baseline (speedup 1.0000x reference)
#include <cuda_runtime.h>
#include <cuda_bf16.h>
#include <cstdint>
#include <cstddef>

// ---------------- problem constants ----------------
#define BATCH   4
#define SEQLEN  2048
#define DMODEL  2048
#define DINNER  4096
#define DSTATE  64
#define NHEADS  32
#define HEADDIM 128
#define CHUNK   256
#define NCHUNK  8
#define CONVDIM (DINNER + 2*DSTATE)           // 4224
#define DINPROJ (DINNER + CONVDIM + NHEADS)   // 8352
#define BL      (BATCH*SEQLEN)                // 8192
#define EPSF    1.1920929e-07f

#define K3_IN   (3*DMODEL)                    // 6144
#define K3_OUT  (3*DINNER)                    // 12288

// ---------------- device scratch ----------------
__device__ float g_proj  [(size_t)BL * DINPROJ];
__device__ float g_xc    [(size_t)BL * CONVDIM];
__device__ float g_dt    [(size_t)BL * NHEADS];
__device__ float g_dtraw8[8][(size_t)BL * NHEADS];
__device__ float g_Acs   [(size_t)BATCH*NCHUNK*NHEADS*CHUNK];
__device__ float g_G     [(size_t)BATCH*NCHUNK*CHUNK*CHUNK];
__device__ float g_states[(size_t)BATCH*NCHUNK*NHEADS*DSTATE*HEADDIM];
__device__ float g_prev  [(size_t)BATCH*NCHUNK*NHEADS*DSTATE*HEADDIM];
__device__ float g_y     [(size_t)BL * DINNER];
// bf16 split-interleaved operands
__device__ __align__(16) __nv_bfloat16 g_x3 [(size_t)BL * K3_IN];       // (hi,hi,lo)
__device__ __align__(16) __nv_bfloat16 g_w3 [(size_t)DINPROJ * K3_IN];  // (hi,lo,hi)
__device__ __align__(16) __nv_bfloat16 g_g3 [(size_t)BL * K3_OUT];      // (hi,hi,lo)
__device__ __align__(16) __nv_bfloat16 g_wo3[(size_t)DMODEL * K3_OUT];  // (hi,lo,hi)

extern __shared__ float smem_dyn[];

// =====================================================================
// helpers
// =====================================================================
__device__ __forceinline__ uint32_t cvta_s(const void* p) {
    return (uint32_t)__cvta_generic_to_shared(p);
}
__device__ __forceinline__ void cp_async16(uint32_t dst, const void* src, uint32_t sz) {
    asm volatile("cp.async.cg.shared.global [%0], [%1], 16, %2;"
                 :: "r"(dst), "l"(src), "r"(sz) : "memory");
}
__device__ __forceinline__ void cp_commit() {
    asm volatile("cp.async.commit_group;" ::: "memory");
}
template <int N>
__device__ __forceinline__ void cp_wait() {
    asm volatile("cp.async.wait_group %0;" :: "n"(N) : "memory");
}
__device__ __forceinline__ void mma16816(float* c, const uint32_t* a, const uint32_t* b) {
    asm volatile(
        "mma.sync.aligned.m16n8k16.row.col.f32.bf16.bf16.f32 "
        "{%0,%1,%2,%3}, {%4,%5,%6,%7}, {%8,%9}, {%0,%1,%2,%3};"
        : "+f"(c[0]), "+f"(c[1]), "+f"(c[2]), "+f"(c[3])
        : "r"(a[0]), "r"(a[1]), "r"(a[2]), "r"(a[3]), "r"(b[0]), "r"(b[1]));
}
__device__ __forceinline__ void ldsm_x4(uint32_t* r, uint32_t addr) {
    asm volatile("ldmatrix.sync.aligned.m8n8.x4.shared.b16 {%0,%1,%2,%3}, [%4];"
                 : "=r"(r[0]), "=r"(r[1]), "=r"(r[2]), "=r"(r[3]) : "r"(addr));
}

// =====================================================================
// mma.sync bf16 GEMM-NT (R14 winner): 128x128 tile, 128 threads (4 warps,
// warp tile 64x64), K-chunk 64, 3-stage ring, 2 CTAs/SM co-residency.
// =====================================================================
#define MSTG      3
#define MKCH      64
#define ASTRIDE   72                        // bf16 elems per smem row (pad)
#define OPA_ELEMS (128*ASTRIDE)
#define OPB_ELEMS (128*ASTRIDE)
#define STG_ELEMS (OPA_ELEMS+OPB_ELEMS)     // 18432 elems
#define GEMM_SMEM (MSTG*STG_ELEMS*2)        // 110592 bytes
#define SUPERM    8

__global__ __launch_bounds__(128, 2)
void gemm_mma(const __nv_bfloat16* __restrict__ A,
              const __nv_bfloat16* __restrict__ B,
              float* __restrict__ C,
              int M, int N, int K3, int tilesN) {
    extern __shared__ __nv_bfloat16 sm[];
    const int tid  = threadIdx.x;
    const int lane = tid & 31;
    const int wid  = tid >> 5;

    const int lin = blockIdx.x;
    const int per = SUPERM * tilesN;
    const int grp = lin / per, rem = lin % per;
    const int m0 = (grp * SUPERM + (rem % SUPERM)) * 128;
    const int n0 = (rem / SUPERM) * 128;

    const int NK = K3 / MKCH;

    const int g  = lane >> 2;
    const int t2 = (lane & 3) * 2;
    const int wr0 = (wid & 1) * 64;
    const int wc0 = (wid >> 1) * 64;

    const uint32_t smBase = cvta_s(sm);

    const int aRow = ((lane >> 3) & 1) * 8 + (lane & 7);
    const int aK   = (lane >> 4) * 8;
    const int bRow = (lane >> 4) * 8 + (lane & 7);
    const int bK   = ((lane >> 3) & 1) * 8;

    auto load_stage = [&](int st, int i) {
        const size_t koff = (size_t)i * MKCH * 2;
        const uint32_t sb = smBase + (uint32_t)st * (STG_ELEMS * 2);
#pragma unroll
        for (int r = 0; r < 16; r++) {
            int idx = tid + r * 128;
            int isB = idx >= 1024;
            int li  = isB ? idx - 1024 : idx;
            int row = li >> 3, c = li & 7;
            uint32_t dst = sb + (uint32_t)isB * (OPA_ELEMS * 2) + row * (ASTRIDE * 2) + c * 16;
            const char* src;
            uint32_t sz = 16;
            if (!isB) {
                src = (const char*)A + ((size_t)(m0 + row) * K3) * 2 + koff + c * 16;
            } else {
                int rr = n0 + row;
                if (rr < N) src = (const char*)B + ((size_t)rr * K3) * 2 + koff + c * 16;
                else { src = (const char*)B; sz = 0; }
            }
            cp_async16(dst, src, sz);
        }
    };

    float acc[4][8][4];
#pragma unroll
    for (int mt = 0; mt < 4; mt++)
#pragma unroll
        for (int nt = 0; nt < 8; nt++)
#pragma unroll
            for (int e = 0; e < 4; e++) acc[mt][nt][e] = 0.f;

    load_stage(0, 0); cp_commit();
    load_stage(1, 1); cp_commit();
    load_stage(2, 2); cp_commit();

    uint32_t afr[2][4][4];
    uint32_t bfr[2][4][4];

    cp_wait<2>();
    __syncthreads();
    {
        const uint32_t sA = smBase;
        const uint32_t sB = sA + OPA_ELEMS * 2;
#pragma unroll
        for (int mt = 0; mt < 4; mt++)
            ldsm_x4(afr[0][mt], sA + ((wr0 + mt * 16 + aRow) * ASTRIDE + aK) * 2);
#pragma unroll
        for (int p = 0; p < 4; p++)
            ldsm_x4(bfr[0][p], sB + ((wc0 + p * 16 + bRow) * ASTRIDE + bK) * 2);
    }

    int slot = 0;
    for (int i = 0; i < NK; i++) {
        const int nslot = (slot + 1 == MSTG) ? 0 : slot + 1;
        const uint32_t sA = smBase + (uint32_t)slot * (STG_ELEMS * 2);
        const uint32_t sB = sA + OPA_ELEMS * 2;
        const uint32_t sAn = smBase + (uint32_t)nslot * (STG_ELEMS * 2);
        const uint32_t sBn = sAn + OPA_ELEMS * 2;

#pragma unroll
        for (int kg = 0; kg < 4; kg++) {
            const int buf = kg & 1;
            const int nb = buf ^ 1;
            if (kg < 3) {
                const int kb = (kg + 1) * 16;
#pragma unroll
                for (int mt = 0; mt < 4; mt++)
                    ldsm_x4(afr[nb][mt], sA + ((wr0 + mt * 16 + aRow) * ASTRIDE + kb + aK) * 2);
#pragma unroll
                for (int p = 0; p < 4; p++)
                    ldsm_x4(bfr[nb][p], sB + ((wc0 + p * 16 + bRow) * ASTRIDE + kb + bK) * 2);
            } else if (i + 1 < NK) {
                cp_wait<1>();
                __syncthreads();
#pragma unroll
                for (int mt = 0; mt < 4; mt++)
                    ldsm_x4(afr[nb][mt], sAn + ((wr0 + mt * 16 + aRow) * ASTRIDE + aK) * 2);
#pragma unroll
                for (int p = 0; p < 4; p++)
                    ldsm_x4(bfr[nb][p], sBn + ((wc0 + p * 16 + bRow) * ASTRIDE + bK) * 2);
                if (i + 3 < NK) load_stage(slot, i + 3);
            }
#pragma unroll
            for (int mt = 0; mt < 4; mt++)
#pragma unroll
                for (int nt = 0; nt < 8; nt++)
                    mma16816(acc[mt][nt], afr[buf][mt], &bfr[buf][nt >> 1][(nt & 1) * 2]);
        }
        cp_commit();
        slot = nslot;
    }

#pragma unroll
    for (int mt = 0; mt < 4; mt++) {
        int r0 = m0 + wr0 + mt * 16 + g;
#pragma unroll
        for (int nt = 0; nt < 8; nt++) {
            int cc = n0 + wc0 + nt * 8 + t2;
            if (cc + 1 < N) {
                *(float2*)(C + (size_t)r0 * N + cc) = make_float2(acc[mt][nt][0], acc[mt][nt][1]);
                *(float2*)(C + (size_t)(r0 + 8) * N + cc) = make_float2(acc[mt][nt][2], acc[mt][nt][3]);
            } else if (cc < N) {
                C[(size_t)r0 * N + cc] = acc[mt][nt][0];
                C[(size_t)(r0 + 8) * N + cc] = acc[mt][nt][2];
            }
        }
    }
}

// =====================================================================
// skinny fp32 GEMM for dt repair, split-K x 8.
// =====================================================================
__global__ __launch_bounds__(256) void gemm_dt(const float* __restrict__ x,
                                               const float* __restrict__ W) {
    __shared__ float xs[32][33];
    __shared__ float Wt[32][33];
    const int t = threadIdx.x;
    const int rc = t >> 3;
    const int k4 = (t & 7) * 4;
    const int w = t >> 5, l = t & 31;
    const int row0 = blockIdx.x * 32;
    const int s = blockIdx.y;
    const int kbeg = s * (DMODEL / 8);

    float acc[4] = {0.f, 0.f, 0.f, 0.f};
    for (int k0 = kbeg; k0 < kbeg + DMODEL / 8; k0 += 32) {
        __syncthreads();
        float4 xv = *(const float4*)(x + (size_t)(row0 + rc) * DMODEL + k0 + k4);
        xs[rc][k4 + 0] = xv.x; xs[rc][k4 + 1] = xv.y;
        xs[rc][k4 + 2] = xv.z; xs[rc][k4 + 3] = xv.w;
        float4 wv = *(const float4*)(W + (size_t)rc * DMODEL + k0 + k4);
        Wt[k4 + 0][rc] = wv.x; Wt[k4 + 1][rc] = wv.y;
        Wt[k4 + 2][rc] = wv.z; Wt[k4 + 3][rc] = wv.w;
        __syncthreads();
#pragma unroll
        for (int kk = 0; kk < 32; kk++) {
            float wl = Wt[kk][l];
#pragma unroll
            for (int r = 0; r < 4; r++)
                acc[r] = fmaf(xs[w * 4 + r][kk], wl, acc[r]);
        }
    }
#pragma unroll
    for (int r = 0; r < 4; r++)
        g_dtraw8[s][(size_t)(row0 + w * 4 + r) * NHEADS + l] = acc[r];
}

// =====================================================================
// split3: fp32 -> interleaved bf16 triples. mode 0: (hi,hi,lo), 1: (hi,lo,hi)
// =====================================================================
__global__ __launch_bounds__(256) void split3(const float* __restrict__ src,
                                              __nv_bfloat16* __restrict__ dst,
                                              size_t n8, int mode) {
    size_t t = (size_t)blockIdx.x * blockDim.x + threadIdx.x;
    if (t >= n8) return;
    const float4* s4 = (const float4*)(src + t * 8);
    float4 a = s4[0], b = s4[1];
    float v[8] = {a.x, a.y, a.z, a.w, b.x, b.y, b.z, b.w};
    unsigned short h[24];
#pragma unroll
    for (int e = 0; e < 8; e++) {
        __nv_bfloat16 hi = __float2bfloat16(v[e]);
        __nv_bfloat16 lo = __float2bfloat16(v[e] - __bfloat162float(hi));
        unsigned short hb = __bfloat16_as_ushort(hi);
        unsigned short lb = __bfloat16_as_ushort(lo);
        h[3 * e] = hb;
        h[3 * e + 1] = mode ? lb : hb;
        h[3 * e + 2] = mode ? hb : lb;
    }
    uint4 w0, w1, w2;
    w0.x = h[0]  | (uint32_t)h[1]  << 16; w0.y = h[2]  | (uint32_t)h[3]  << 16;
    w0.z = h[4]  | (uint32_t)h[5]  << 16; w0.w = h[6]  | (uint32_t)h[7]  << 16;
    w1.x = h[8]  | (uint32_t)h[9]  << 16; w1.y = h[10] | (uint32_t)h[11] << 16;
    w1.z = h[12] | (uint32_t)h[13] << 16; w1.w = h[14] | (uint32_t)h[15] << 16;
    w2.x = h[16] | (uint32_t)h[17] << 16; w2.y = h[18] | (uint32_t)h[19] << 16;
    w2.z = h[20] | (uint32_t)h[21] << 16; w2.w = h[22] | (uint32_t)h[23] << 16;
    uint4* d4 = (uint4*)((char*)dst + t * 48);
    d4[0] = w0; d4[1] = w1; d4[2] = w2;
}

// =====================================================================
// Tiled causal conv1d (width 4) + bias + SiLU over xBC slice of proj.
// =====================================================================
__global__ __launch_bounds__(256) void conv_silu_tiled(const float* __restrict__ conv_w,
                                                       const float* __restrict__ conv_b) {
    __shared__ float xs[67][128];
    __shared__ float ws[128][4];
    __shared__ float bs[128];

    const int tid = threadIdx.x;
    const int b   = blockIdx.x >> 5;
    const int l0  = (blockIdx.x & 31) * 64;
    const int c0  = blockIdx.y * 128;

    if (tid < 128) {
        float4 w4 = *(const float4*)(conv_w + (size_t)(c0 + tid) * 4);
        ws[tid][0] = w4.x; ws[tid][1] = w4.y; ws[tid][2] = w4.z; ws[tid][3] = w4.w;
        bs[tid] = conv_b[c0 + tid];
    }

    for (int idx = tid; idx < 67 * 32; idx += 256) {
        int row = idx >> 5, c4 = (idx & 31) * 4;
        int l = l0 - 3 + row;
        float4 v = make_float4(0.f, 0.f, 0.f, 0.f);
        if (l >= 0)
            v = *(const float4*)(g_proj + (size_t)(b * SEQLEN + l) * DINPROJ + DINNER + c0 + c4);
        *(float4*)&xs[row][c4] = v;
    }
    __syncthreads();

    for (int idx = tid; idx < 64 * 32; idx += 256) {
        int row = idx >> 5, c4 = (idx & 31) * 4;
        float o[4];
#pragma unroll
        for (int e = 0; e < 4; e++) {
            int c = c4 + e;
            float acc = bs[c];
#pragma unroll
            for (int k = 0; k < 4; k++)
                acc = fmaf(xs[row + k][c], ws[c][k], acc);
            o[e] = acc * (1.f / (1.f + __expf(-acc)));
        }
        *(float4*)(g_xc + (size_t)(b * SEQLEN + l0 + row) * CONVDIM + c0 + c4) =
            make_float4(o[0], o[1], o[2], o[3]);
    }
}

// =====================================================================
// dt = softplus(sum of split-K partials + bias); cumsum(dA) per chunk
// =====================================================================
__global__ __launch_bounds__(256) void dt_scan(const float* __restrict__ A_log,
                                               const float* __restrict__ dt_bias) {
    const int bx = blockIdx.x;
    const int h  = bx & 31;
    const int q  = threadIdx.x;
    const int c  = (bx >> 5) & 7;
    const int b  = bx >> 8;
    const int bl = b * SEQLEN + c * CHUNK + q;

    float v = dt_bias[h];
#pragma unroll
    for (int s = 0; s < 8; s++) v += g_dtraw8[s][(size_t)bl * NHEADS + h];
    float dt = (v > 20.f) ? v : log1pf(__expf(v));
    g_dt[(size_t)bl * NHEADS + h] = dt;
    float dA = dt * (-__expf(A_log[h]));

    const int lane = q & 31, warp = q >> 5;
    float sv = dA;
#pragma unroll
    for (int off = 1; off < 32; off <<= 1) {
        float t = __shfl_up_sync(0xFFFFFFFFu, sv, off);
        if (lane >= off) sv += t;
    }
    __shared__ float wsum[8];
    if (lane == 31) wsum[warp] = sv;
    __syncthreads();
    float add = 0.f;
#pragma unroll
    for (int w = 0; w < 8; w++)
        if (w < warp) add += wsum[w];
    g_Acs[(size_t)bx * CHUNK + q] = sv + add;
}

// =====================================================================
// G[b,c,q,k] = sum_n C[q,n] * B[k,n]  — triangular grid: 10 tiles only
// =====================================================================
__constant__ int c_qt10[10] = {0, 1, 1, 2, 2, 2, 3, 3, 3, 3};
__constant__ int c_kt10[10] = {0, 0, 1, 0, 1, 2, 0, 1, 2, 3};

__global__ __launch_bounds__(256) void compute_G() {
    const int bc = blockIdx.x;
    const int q0 = c_qt10[blockIdx.y] * 64;
    const int k0 = c_kt10[blockIdx.y] * 64;

    __shared__ float Cs[64][65];
    __shared__ float Bs[64][65];
    const int tid = threadIdx.x;
    const int bl0 = (bc >> 3) * SEQLEN + (bc & 7) * CHUNK;

#pragma unroll
    for (int r = 0; r < 16; r++) {
        int idx = tid + r * 256;
        int row = idx >> 6, col = idx & 63;
        Cs[row][col] = g_xc[(size_t)(bl0 + q0 + row) * CONVDIM + DINNER + DSTATE + col];
        Bs[row][col] = g_xc[(size_t)(bl0 + k0 + row) * CONVDIM + DINNER + col];
    }
    __syncthreads();

    const int tx = tid & 15, ty = tid >> 4;
    float acc[4][4];
#pragma unroll
    for (int i = 0; i < 4; i++)
#pragma unroll
        for (int j = 0; j < 4; j++) acc[i][j] = 0.f;

    for (int n = 0; n < 64; n++) {
        float a[4], b[4];
#pragma unroll
        for (int i = 0; i < 4; i++) a[i] = Cs[ty * 4 + i][n];
#pragma unroll
        for (int j = 0; j < 4; j++) b[j] = Bs[tx * 4 + j][n];
#pragma unroll
        for (int i = 0; i < 4; i++)
#pragma unroll
            for (int j = 0; j < 4; j++) acc[i][j] = fmaf(a[i], b[j], acc[i][j]);
    }
#pragma unroll
    for (int i = 0; i < 4; i++)
#pragma unroll
        for (int j = 0; j < 4; j++)
            g_G[((size_t)bc * CHUNK + q0 + ty * 4 + i) * CHUNK + k0 + tx * 4 + j] = acc[i][j];
}

// =====================================================================
// states: per-chunk B^T (decay * x*dt) — 128 threads, 8x8 per thread
// (LDS per FMA cut 33% vs 4x8; same tiles, same smem, 3 CTAs/SM)
// =====================================================================
__global__ __launch_bounds__(128, 3) void compute_states() {
    const int bx = blockIdx.x;
    const int h  = bx & 31;
    const int c  = (bx >> 5) & 7;
    const int b  = bx >> 8;
    const int bl0 = b * SEQLEN + c * CHUNK;

    float* Acs_s = smem_dyn;
    float* dt_s  = smem_dyn + 256;
    float* Bs    = smem_dyn + 512;
    float* Xs    = Bs + 64 * 65;

    const int tid = threadIdx.x;
    Acs_s[tid]       = g_Acs[(size_t)bx * CHUNK + tid];
    Acs_s[tid + 128] = g_Acs[(size_t)bx * CHUNK + tid + 128];
    dt_s[tid]        = g_dt[(size_t)(bl0 + tid) * NHEADS + h];
    dt_s[tid + 128]  = g_dt[(size_t)(bl0 + tid + 128) * NHEADS + h];
    __syncthreads();
    const float Alast = Acs_s[255];

    const int tx = tid & 15, ty = tid >> 4;   // 16 x 8 grid, 8x8 each
    float acc[8][8];
#pragma unroll
    for (int i = 0; i < 8; i++)
#pragma unroll
        for (int j = 0; j < 8; j++) acc[i][j] = 0.f;

    for (int kt = 0; kt < 4; kt++) {
        const int k0 = kt * 64;
        __syncthreads();
#pragma unroll
        for (int r = 0; r < 32; r++) {
            int idx = tid + r * 128;
            int kk = idx >> 6, n = idx & 63;
            float dec = __expf(Alast - Acs_s[k0 + kk]);
            Bs[kk * 65 + n] = g_xc[(size_t)(bl0 + k0 + kk) * CONVDIM + DINNER + n] * dec;
        }
#pragma unroll
        for (int r = 0; r < 16; r++) {
            int f4 = tid + r * 128;
            int kk = f4 >> 5, p4 = f4 & 31;
            float4 v = *(const float4*)(g_xc + (size_t)(bl0 + k0 + kk) * CONVDIM + h * HEADDIM + p4 * 4);
            float d = dt_s[k0 + kk];
            v.x *= d; v.y *= d; v.z *= d; v.w *= d;
            *(float4*)(Xs + kk * 128 + p4 * 4) = v;
        }
        __syncthreads();
        for (int kk = 0; kk < 64; kk++) {
            float a[8], bb[8];
#pragma unroll
            for (int i = 0; i < 8; i++) a[i] = Bs[kk * 65 + ty * 8 + i];
            *(float4*)&bb[0] = *(const float4*)(Xs + kk * 128 + tx * 8);
            *(float4*)&bb[4] = *(const float4*)(Xs + kk * 128 + tx * 8 + 4);
#pragma unroll
            for (int i = 0; i < 8; i++)
#pragma unroll
                for (int j = 0; j < 8; j++) acc[i][j] = fmaf(a[i], bb[j], acc[i][j]);
        }
    }

    size_t base = (size_t)bx * (DSTATE * HEADDIM);
#pragma unroll
    for (int i = 0; i < 8; i++) {
        int n = ty * 8 + i;
        *(float4*)(g_states + base + (size_t)n * 128 + tx * 8) =
            make_float4(acc[i][0], acc[i][1], acc[i][2], acc[i][3]);
        *(float4*)(g_states + base + (size_t)n * 128 + tx * 8 + 4) =
            make_float4(acc[i][4], acc[i][5], acc[i][6], acc[i][7]);
    }
}

// =====================================================================
// inter-chunk scan
// =====================================================================
__global__ __launch_bounds__(256) void chunk_scan() {
    const int bh = blockIdx.x;
    const int b = bh >> 5, h = bh & 31;
    __shared__ float cd[NCHUNK];
    if (threadIdx.x < NCHUNK) {
        int c = threadIdx.x;
        cd[c] = __expf(g_Acs[(size_t)(((b * 8 + c) * 32) + h) * CHUNK + 255]);
    }
    __syncthreads();
    for (int e = threadIdx.x; e < DSTATE * HEADDIM; e += 256) {
        float carry = 0.f;
#pragma unroll
        for (int c = 0; c < NCHUNK; c++) {
            size_t idx = (size_t)(((b * 8 + c) * 32) + h) * (DSTATE * HEADDIM) + e;
            g_prev[idx] = carry;
            carry = carry * cd[c] + g_states[idx];
        }
    }
}

// =====================================================================
// Y = diag + off + x*D — 128 threads, 8x8 per thread; 64-row q tiles;
// off-diagonal W fill unguarded.
// =====================================================================
__global__ __launch_bounds__(128, 3) void compute_Y(const float* __restrict__ Dp) {
    const int bx = blockIdx.x;
    const int h  = bx & 31;
    const int bc = bx >> 5;
    const int c  = bc & 7;
    const int b  = bc >> 3;
    const int bl0 = b * SEQLEN + c * CHUNK;

    float* Acs_s = smem_dyn;
    float* dt_s  = smem_dyn + 256;
    float* Ws    = smem_dyn + 512;
    float* Xs    = Ws + 64 * 65;

    const int tid = threadIdx.x;
    Acs_s[tid]       = g_Acs[(size_t)bx * CHUNK + tid];
    Acs_s[tid + 128] = g_Acs[(size_t)bx * CHUNK + tid + 128];
    dt_s[tid]        = g_dt[(size_t)(bl0 + tid) * NHEADS + h];
    dt_s[tid + 128]  = g_dt[(size_t)(bl0 + tid + 128) * NHEADS + h];
    __syncthreads();

    const int tx = tid & 15, ty = tid >> 4;   // 16 x 8 grid, 8x8 each
    const float Dh = Dp[h];

    for (int qt = 0; qt < 4; qt++) {
        const int q0 = qt * 64;
        float acc[8][8];
#pragma unroll
        for (int i = 0; i < 8; i++)
#pragma unroll
            for (int j = 0; j < 8; j++) acc[i][j] = 0.f;

        for (int kt = 0; kt <= qt; kt++) {
            const int k0 = kt * 64;
            __syncthreads();
            if (kt < qt) {
#pragma unroll
                for (int r = 0; r < 32; r++) {
                    int idx = tid + r * 128;
                    int qq = idx >> 6, kk = idx & 63;
                    int q = q0 + qq, k = k0 + kk;
                    Ws[qq * 65 + kk] = g_G[((size_t)bc * CHUNK + q) * CHUNK + k]
                                       * __expf(Acs_s[q] - Acs_s[k]);
                }
            } else {
#pragma unroll
                for (int r = 0; r < 32; r++) {
                    int idx = tid + r * 128;
                    int qq = idx >> 6, kk = idx & 63;
                    int q = q0 + qq, k = k0 + kk;
                    float w = 0.f;
                    if (k <= q)
                        w = g_G[((size_t)bc * CHUNK + q) * CHUNK + k]
                            * __expf(Acs_s[q] - Acs_s[k]);
                    Ws[qq * 65 + kk] = w;
                }
            }
#pragma unroll
            for (int r = 0; r < 16; r++) {
                int f4 = tid + r * 128;
                int kk = f4 >> 5, p4 = f4 & 31;
                float4 v = *(const float4*)(g_xc + (size_t)(bl0 + k0 + kk) * CONVDIM + h * HEADDIM + p4 * 4);
                float d = dt_s[k0 + kk];
                v.x *= d; v.y *= d; v.z *= d; v.w *= d;
                *(float4*)(Xs + kk * 128 + p4 * 4) = v;
            }
            __syncthreads();
            for (int kk = 0; kk < 64; kk++) {
                float a[8], bb[8];
#pragma unroll
                for (int i = 0; i < 8; i++) a[i] = Ws[(ty * 8 + i) * 65 + kk];
                *(float4*)&bb[0] = *(const float4*)(Xs + kk * 128 + tx * 8);
                *(float4*)&bb[4] = *(const float4*)(Xs + kk * 128 + tx * 8 + 4);
#pragma unroll
                for (int i = 0; i < 8; i++)
#pragma unroll
                    for (int j = 0; j < 8; j++) acc[i][j] = fmaf(a[i], bb[j], acc[i][j]);
            }
        }

        // ---- Y_off: (C * e^{Acs_q}) @ prev ----
        __syncthreads();
#pragma unroll
        for (int r = 0; r < 32; r++) {
            int idx = tid + r * 128;
            int qq = idx >> 6, n = idx & 63;
            Ws[qq * 65 + n] = g_xc[(size_t)(bl0 + q0 + qq) * CONVDIM + DINNER + DSTATE + n]
                              * __expf(Acs_s[q0 + qq]);
        }
#pragma unroll
        for (int r = 0; r < 16; r++) {
            int f4 = tid + r * 128;
            int n = f4 >> 5, p4 = f4 & 31;
            *(float4*)(Xs + n * 128 + p4 * 4) =
                *(const float4*)(g_prev + (size_t)bx * (DSTATE * HEADDIM) + (size_t)n * 128 + p4 * 4);
        }
        __syncthreads();
        for (int n = 0; n < 64; n++) {
            float a[8], bb[8];
#pragma unroll
            for (int i = 0; i < 8; i++) a[i] = Ws[(ty * 8 + i) * 65 + n];
            *(float4*)&bb[0] = *(const float4*)(Xs + n * 128 + tx * 8);
            *(float4*)&bb[4] = *(const float4*)(Xs + n * 128 + tx * 8 + 4);
#pragma unroll
            for (int i = 0; i < 8; i++)
#pragma unroll
                for (int j = 0; j < 8; j++) acc[i][j] = fmaf(a[i], bb[j], acc[i][j]);
        }

        // ---- add x*D, store ----
#pragma unroll
        for (int i = 0; i < 8; i++) {
            int q = q0 + ty * 8 + i;
            const float* xr = g_xc + (size_t)(bl0 + q) * CONVDIM + h * HEADDIM + tx * 8;
            float* yr = g_y + (size_t)(bl0 + q) * DINNER + h * HEADDIM + tx * 8;
#pragma unroll
            for (int j = 0; j < 8; j++) yr[j] = acc[i][j] + xr[j] * Dh;
        }
    }
}

// =====================================================================
// RMSNorm + SiLU gate, fused with split3(mode 0) -> writes g_g3 directly
// =====================================================================
__global__ __launch_bounds__(256) void rmsnorm_gate_split() {
    const int bl = blockIdx.x;
    const float* y = g_y + (size_t)bl * DINNER;
    const float* z = g_proj + (size_t)bl * DINPROJ;

    float ss = 0.f;
    for (int i = threadIdx.x * 4; i < DINNER; i += 256 * 4) {
        float4 v = *(const float4*)(y + i);
        ss += v.x * v.x + v.y * v.y + v.z * v.z + v.w * v.w;
    }
    __shared__ float red[256];
    red[threadIdx.x] = ss;
    __syncthreads();
    for (int s = 128; s > 0; s >>= 1) {
        if (threadIdx.x < s) red[threadIdx.x] += red[threadIdx.x + s];
        __syncthreads();
    }
    float r = rsqrtf(red[0] / (float)DINNER + EPSF);

    for (int i = threadIdx.x * 8; i < DINNER; i += 256 * 8) {
        float4 y0 = *(const float4*)(y + i);
        float4 y1 = *(const float4*)(y + i + 4);
        float4 z0 = *(const float4*)(z + i);
        float4 z1 = *(const float4*)(z + i + 4);
        float v[8];
        float zz[8] = {z0.x, z0.y, z0.z, z0.w, z1.x, z1.y, z1.z, z1.w};
        float yy[8] = {y0.x, y0.y, y0.z, y0.w, y1.x, y1.y, y1.z, y1.w};
#pragma unroll
        for (int e = 0; e < 8; e++)
            v[e] = yy[e] * r * (zz[e] / (1.f + __expf(-zz[e])));
        unsigned short h[24];
#pragma unroll
        for (int e = 0; e < 8; e++) {
            __nv_bfloat16 hi = __float2bfloat16(v[e]);
            __nv_bfloat16 lo = __float2bfloat16(v[e] - __bfloat162float(hi));
            unsigned short hb = __bfloat16_as_ushort(hi);
            unsigned short lb = __bfloat16_as_ushort(lo);
            h[3 * e] = hb; h[3 * e + 1] = hb; h[3 * e + 2] = lb;
        }
        uint4 w0, w1, w2;
        w0.x = h[0]  | (uint32_t)h[1]  << 16; w0.y = h[2]  | (uint32_t)h[3]  << 16;
        w0.z = h[4]  | (uint32_t)h[5]  << 16; w0.w = h[6]  | (uint32_t)h[7]  << 16;
        w1.x = h[8]  | (uint32_t)h[9]  << 16; w1.y = h[10] | (uint32_t)h[11] << 16;
        w1.z = h[12] | (uint32_t)h[13] << 16; w1.w = h[14] | (uint32_t)h[15] << 16;
        w2.x = h[16] | (uint32_t)h[17] << 16; w2.y = h[18] | (uint32_t)h[19] << 16;
        w2.z = h[20] | (uint32_t)h[21] << 16; w2.w = h[22] | (uint32_t)h[23] << 16;
        uint4* d4 = (uint4*)((char*)g_g3 + ((size_t)bl * K3_OUT + 3 * (size_t)i) * 2);
        d4[0] = w0; d4[1] = w1; d4[2] = w2;
    }
}

// =====================================================================
// launch
// =====================================================================
extern "C" void kernel_launch(void* const* d_in, const int* in_sizes, int n_in,
                              void* d_out, int out_size) {
    const float* x       = (const float*)d_in[0];
    const float* W_in    = (const float*)d_in[1];
    const float* conv_w  = (const float*)d_in[2];
    const float* conv_b  = (const float*)d_in[3];
    const float* A_log   = (const float*)d_in[4];
    const float* dt_bias = (const float*)d_in[5];
    const float* Dp      = (const float*)d_in[6];
    const float* W_out   = (const float*)d_in[7];
    float* out = (float*)d_out;

    float *p_proj = nullptr;
    __nv_bfloat16 *p_x3, *p_w3, *p_g3, *p_wo3;
    cudaGetSymbolAddress((void**)&p_proj, g_proj);
    cudaGetSymbolAddress((void**)&p_x3, g_x3);
    cudaGetSymbolAddress((void**)&p_w3, g_w3);
    cudaGetSymbolAddress((void**)&p_g3, g_g3);
    cudaGetSymbolAddress((void**)&p_wo3, g_wo3);

    const int SMEM_DYN = (512 + 64 * 65 + 64 * 128) * 4;   // 51456
    cudaFuncSetAttribute((const void*)compute_states,
                         cudaFuncAttributeMaxDynamicSharedMemorySize, SMEM_DYN);
    cudaFuncSetAttribute((const void*)compute_Y,
                         cudaFuncAttributeMaxDynamicSharedMemorySize, SMEM_DYN);
    cudaFuncSetAttribute((const void*)gemm_mma,
                         cudaFuncAttributeMaxDynamicSharedMemorySize, GEMM_SMEM);

    // --- split operands for GEMM1 ---
    split3<<<(unsigned)(((size_t)BL * DMODEL / 8 + 255) / 256), 256>>>(x, p_x3, (size_t)BL * DMODEL / 8, 0);
    {
        size_t halfRows = DINPROJ / 2;                       // 4176
        size_t n8 = halfRows * DMODEL / 8;
        split3<<<(unsigned)((n8 + 255) / 256), 256>>>(W_in, p_w3, n8, 1);
        split3<<<(unsigned)((n8 + 255) / 256), 256>>>(W_in + halfRows * DMODEL,
                                                      p_w3 + halfRows * K3_IN, n8, 1);
    }

    // --- GEMM1 (tensor cores): proj = x @ W_in^T ---
    {
        int tilesN = (DINPROJ + 127) / 128;   // 66
        int tilesM = BL / 128;                // 64
        gemm_mma<<<tilesM * tilesN, 128, GEMM_SMEM>>>(
            p_x3, p_w3, p_proj, BL, DINPROJ, K3_IN, tilesN);
    }

    // --- dt repair GEMM (exact fp32, split-K x 8) ---
    gemm_dt<<<dim3(BL / 32, 8), 256>>>(x, W_in + (size_t)(DINNER + CONVDIM) * DMODEL);

    // --- conv + silu (tiled, read-once) ---
    conv_silu_tiled<<<dim3(BATCH * (SEQLEN / 64), CONVDIM / 128), 256>>>(conv_w, conv_b);

    // --- dt, cumsum(dA) ---
    dt_scan<<<BATCH * NCHUNK * NHEADS, 256>>>(A_log, dt_bias);

    // --- SSD ---
    compute_G<<<dim3(BATCH * NCHUNK, 10), 256>>>();
    compute_states<<<BATCH * NCHUNK * NHEADS, 128, SMEM_DYN>>>();
    chunk_scan<<<BATCH * NHEADS, 256>>>();
    compute_Y<<<BATCH * NCHUNK * NHEADS, 128, SMEM_DYN>>>(Dp);

    // --- rmsnorm + gate + split (fused) ---
    rmsnorm_gate_split<<<BL, 256>>>();

    // --- split weights for GEMM2 ---
    split3<<<(unsigned)(((size_t)DMODEL * DINNER / 8 + 255) / 256), 256>>>(W_out, p_wo3, (size_t)DMODEL * DINNER / 8, 1);

    // --- GEMM2 (tensor cores): out = gated @ W_out^T ---
    {
        int tilesN = DMODEL / 128;            // 16
        int tilesM = BL / 128;                // 64
        gemm_mma<<<tilesM * tilesN, 128, GEMM_SMEM>>>(
            p_g3, p_wo3, out, BL, DMODEL, K3_OUT, tilesN);
    }
}

// round 16
// speedup vs baseline: 1.0367x; 1.0367x over previous
#include <cuda_runtime.h>
#include <cuda_bf16.h>
#include <cstdint>
#include <cstddef>

// ---------------- problem constants ----------------
#define BATCH   4
#define SEQLEN  2048
#define DMODEL  2048
#define DINNER  4096
#define DSTATE  64
#define NHEADS  32
#define HEADDIM 128
#define CHUNK   256
#define NCHUNK  8
#define CONVDIM (DINNER + 2*DSTATE)           // 4224
#define DINPROJ (DINNER + CONVDIM + NHEADS)   // 8352
#define BL      (BATCH*SEQLEN)                // 8192
#define EPSF    1.1920929e-07f

#define K3_IN   (3*DMODEL)                    // 6144
#define K3_OUT  (3*DINNER)                    // 12288

// ---------------- device scratch ----------------
__device__ float g_proj  [(size_t)BL * DINPROJ];
__device__ float g_xc    [(size_t)BL * CONVDIM];
__device__ float g_dt    [(size_t)BL * NHEADS];
__device__ float g_dtraw8[8][(size_t)BL * NHEADS];
__device__ float g_Acs   [(size_t)BATCH*NCHUNK*NHEADS*CHUNK];
__device__ float g_G     [(size_t)BATCH*NCHUNK*CHUNK*CHUNK];
__device__ float g_states[(size_t)BATCH*NCHUNK*NHEADS*DSTATE*HEADDIM];
__device__ float g_prev  [(size_t)BATCH*NCHUNK*NHEADS*DSTATE*HEADDIM];
__device__ float g_y     [(size_t)BL * DINNER];
// bf16 split-interleaved operands
__device__ __align__(16) __nv_bfloat16 g_x3 [(size_t)BL * K3_IN];       // (hi,hi,lo)
__device__ __align__(16) __nv_bfloat16 g_w3 [(size_t)DINPROJ * K3_IN];  // (hi,lo,hi)
__device__ __align__(16) __nv_bfloat16 g_g3 [(size_t)BL * K3_OUT];      // (hi,hi,lo)
__device__ __align__(16) __nv_bfloat16 g_wo3[(size_t)DMODEL * K3_OUT];  // (hi,lo,hi)

extern __shared__ float smem_dyn[];

// =====================================================================
// helpers
// =====================================================================
__device__ __forceinline__ uint32_t cvta_s(const void* p) {
    return (uint32_t)__cvta_generic_to_shared(p);
}
__device__ __forceinline__ void cp_async16(uint32_t dst, const void* src, uint32_t sz) {
    asm volatile("cp.async.cg.shared.global [%0], [%1], 16, %2;"
                 :: "r"(dst), "l"(src), "r"(sz) : "memory");
}
__device__ __forceinline__ void cp_commit() {
    asm volatile("cp.async.commit_group;" ::: "memory");
}
template <int N>
__device__ __forceinline__ void cp_wait() {
    asm volatile("cp.async.wait_group %0;" :: "n"(N) : "memory");
}
__device__ __forceinline__ void mma16816(float* c, const uint32_t* a, const uint32_t* b) {
    asm volatile(
        "mma.sync.aligned.m16n8k16.row.col.f32.bf16.bf16.f32 "
        "{%0,%1,%2,%3}, {%4,%5,%6,%7}, {%8,%9}, {%0,%1,%2,%3};"
        : "+f"(c[0]), "+f"(c[1]), "+f"(c[2]), "+f"(c[3])
        : "r"(a[0]), "r"(a[1]), "r"(a[2]), "r"(a[3]), "r"(b[0]), "r"(b[1]));
}
__device__ __forceinline__ void ldsm_x4(uint32_t* r, uint32_t addr) {
    asm volatile("ldmatrix.sync.aligned.m8n8.x4.shared.b16 {%0,%1,%2,%3}, [%4];"
                 : "=r"(r[0]), "=r"(r[1]), "=r"(r[2]), "=r"(r[3]) : "r"(addr));
}

// =====================================================================
// mma.sync bf16 GEMM-NT (R14 winner): 128x128 tile, 128 threads (4 warps,
// warp tile 64x64), K-chunk 64, 3-stage ring, 2 CTAs/SM co-residency.
// kg3 slot: refill cp.asyncs issued BEFORE the next-kg0 ldsm pair.
// =====================================================================
#define MSTG      3
#define MKCH      64
#define ASTRIDE   72                        // bf16 elems per smem row (pad)
#define OPA_ELEMS (128*ASTRIDE)
#define OPB_ELEMS (128*ASTRIDE)
#define STG_ELEMS (OPA_ELEMS+OPB_ELEMS)     // 18432 elems
#define GEMM_SMEM (MSTG*STG_ELEMS*2)        // 110592 bytes
#define SUPERM    8

__global__ __launch_bounds__(128, 2)
void gemm_mma(const __nv_bfloat16* __restrict__ A,
              const __nv_bfloat16* __restrict__ B,
              float* __restrict__ C,
              int M, int N, int K3, int tilesN) {
    extern __shared__ __nv_bfloat16 sm[];
    const int tid  = threadIdx.x;
    const int lane = tid & 31;
    const int wid  = tid >> 5;

    const int lin = blockIdx.x;
    const int per = SUPERM * tilesN;
    const int grp = lin / per, rem = lin % per;
    const int m0 = (grp * SUPERM + (rem % SUPERM)) * 128;
    const int n0 = (rem / SUPERM) * 128;

    const int NK = K3 / MKCH;

    const int g  = lane >> 2;
    const int t2 = (lane & 3) * 2;
    const int wr0 = (wid & 1) * 64;
    const int wc0 = (wid >> 1) * 64;

    const uint32_t smBase = cvta_s(sm);

    const int aRow = ((lane >> 3) & 1) * 8 + (lane & 7);
    const int aK   = (lane >> 4) * 8;
    const int bRow = (lane >> 4) * 8 + (lane & 7);
    const int bK   = ((lane >> 3) & 1) * 8;

    auto load_stage = [&](int st, int i) {
        const size_t koff = (size_t)i * MKCH * 2;
        const uint32_t sb = smBase + (uint32_t)st * (STG_ELEMS * 2);
#pragma unroll
        for (int r = 0; r < 16; r++) {
            int idx = tid + r * 128;
            int isB = idx >= 1024;
            int li  = isB ? idx - 1024 : idx;
            int row = li >> 3, c = li & 7;
            uint32_t dst = sb + (uint32_t)isB * (OPA_ELEMS * 2) + row * (ASTRIDE * 2) + c * 16;
            const char* src;
            uint32_t sz = 16;
            if (!isB) {
                src = (const char*)A + ((size_t)(m0 + row) * K3) * 2 + koff + c * 16;
            } else {
                int rr = n0 + row;
                if (rr < N) src = (const char*)B + ((size_t)rr * K3) * 2 + koff + c * 16;
                else { src = (const char*)B; sz = 0; }
            }
            cp_async16(dst, src, sz);
        }
    };

    float acc[4][8][4];
#pragma unroll
    for (int mt = 0; mt < 4; mt++)
#pragma unroll
        for (int nt = 0; nt < 8; nt++)
#pragma unroll
            for (int e = 0; e < 4; e++) acc[mt][nt][e] = 0.f;

    load_stage(0, 0); cp_commit();
    load_stage(1, 1); cp_commit();
    load_stage(2, 2); cp_commit();

    uint32_t afr[2][4][4];
    uint32_t bfr[2][4][4];

    cp_wait<2>();
    __syncthreads();
    {
        const uint32_t sA = smBase;
        const uint32_t sB = sA + OPA_ELEMS * 2;
#pragma unroll
        for (int mt = 0; mt < 4; mt++)
            ldsm_x4(afr[0][mt], sA + ((wr0 + mt * 16 + aRow) * ASTRIDE + aK) * 2);
#pragma unroll
        for (int p = 0; p < 4; p++)
            ldsm_x4(bfr[0][p], sB + ((wc0 + p * 16 + bRow) * ASTRIDE + bK) * 2);
    }

    int slot = 0;
    for (int i = 0; i < NK; i++) {
        const int nslot = (slot + 1 == MSTG) ? 0 : slot + 1;
        const uint32_t sA = smBase + (uint32_t)slot * (STG_ELEMS * 2);
        const uint32_t sB = sA + OPA_ELEMS * 2;
        const uint32_t sAn = smBase + (uint32_t)nslot * (STG_ELEMS * 2);
        const uint32_t sBn = sAn + OPA_ELEMS * 2;

#pragma unroll
        for (int kg = 0; kg < 4; kg++) {
            const int buf = kg & 1;
            const int nb = buf ^ 1;
            if (kg < 3) {
                const int kb = (kg + 1) * 16;
#pragma unroll
                for (int mt = 0; mt < 4; mt++)
                    ldsm_x4(afr[nb][mt], sA + ((wr0 + mt * 16 + aRow) * ASTRIDE + kb + aK) * 2);
#pragma unroll
                for (int p = 0; p < 4; p++)
                    ldsm_x4(bfr[nb][p], sB + ((wc0 + p * 16 + bRow) * ASTRIDE + kb + bK) * 2);
            } else if (i + 1 < NK) {
                // stage i+1 arrival + barrier; then refill the freed slot
                // FIRST (cp.asyncs queue early), then next kg0 ldsm.
                cp_wait<1>();
                __syncthreads();
                if (i + 3 < NK) load_stage(slot, i + 3);
#pragma unroll
                for (int mt = 0; mt < 4; mt++)
                    ldsm_x4(afr[nb][mt], sAn + ((wr0 + mt * 16 + aRow) * ASTRIDE + aK) * 2);
#pragma unroll
                for (int p = 0; p < 4; p++)
                    ldsm_x4(bfr[nb][p], sBn + ((wc0 + p * 16 + bRow) * ASTRIDE + bK) * 2);
            }
#pragma unroll
            for (int mt = 0; mt < 4; mt++)
#pragma unroll
                for (int nt = 0; nt < 8; nt++)
                    mma16816(acc[mt][nt], afr[buf][mt], &bfr[buf][nt >> 1][(nt & 1) * 2]);
        }
        cp_commit();
        slot = nslot;
    }

#pragma unroll
    for (int mt = 0; mt < 4; mt++) {
        int r0 = m0 + wr0 + mt * 16 + g;
#pragma unroll
        for (int nt = 0; nt < 8; nt++) {
            int cc = n0 + wc0 + nt * 8 + t2;
            if (cc + 1 < N) {
                *(float2*)(C + (size_t)r0 * N + cc) = make_float2(acc[mt][nt][0], acc[mt][nt][1]);
                *(float2*)(C + (size_t)(r0 + 8) * N + cc) = make_float2(acc[mt][nt][2], acc[mt][nt][3]);
            } else if (cc < N) {
                C[(size_t)r0 * N + cc] = acc[mt][nt][0];
                C[(size_t)(r0 + 8) * N + cc] = acc[mt][nt][2];
            }
        }
    }
}

// =====================================================================
// skinny fp32 GEMM for dt repair, split-K x 8.
// =====================================================================
__global__ __launch_bounds__(256) void gemm_dt(const float* __restrict__ x,
                                               const float* __restrict__ W) {
    __shared__ float xs[32][33];
    __shared__ float Wt[32][33];
    const int t = threadIdx.x;
    const int rc = t >> 3;
    const int k4 = (t & 7) * 4;
    const int w = t >> 5, l = t & 31;
    const int row0 = blockIdx.x * 32;
    const int s = blockIdx.y;
    const int kbeg = s * (DMODEL / 8);

    float acc[4] = {0.f, 0.f, 0.f, 0.f};
    for (int k0 = kbeg; k0 < kbeg + DMODEL / 8; k0 += 32) {
        __syncthreads();
        float4 xv = *(const float4*)(x + (size_t)(row0 + rc) * DMODEL + k0 + k4);
        xs[rc][k4 + 0] = xv.x; xs[rc][k4 + 1] = xv.y;
        xs[rc][k4 + 2] = xv.z; xs[rc][k4 + 3] = xv.w;
        float4 wv = *(const float4*)(W + (size_t)rc * DMODEL + k0 + k4);
        Wt[k4 + 0][rc] = wv.x; Wt[k4 + 1][rc] = wv.y;
        Wt[k4 + 2][rc] = wv.z; Wt[k4 + 3][rc] = wv.w;
        __syncthreads();
#pragma unroll
        for (int kk = 0; kk < 32; kk++) {
            float wl = Wt[kk][l];
#pragma unroll
            for (int r = 0; r < 4; r++)
                acc[r] = fmaf(xs[w * 4 + r][kk], wl, acc[r]);
        }
    }
#pragma unroll
    for (int r = 0; r < 4; r++)
        g_dtraw8[s][(size_t)(row0 + w * 4 + r) * NHEADS + l] = acc[r];
}

// =====================================================================
// split3: fp32 -> interleaved bf16 triples. mode 0: (hi,hi,lo), 1: (hi,lo,hi)
// =====================================================================
__global__ __launch_bounds__(256) void split3(const float* __restrict__ src,
                                              __nv_bfloat16* __restrict__ dst,
                                              size_t n8, int mode) {
    size_t t = (size_t)blockIdx.x * blockDim.x + threadIdx.x;
    if (t >= n8) return;
    const float4* s4 = (const float4*)(src + t * 8);
    float4 a = s4[0], b = s4[1];
    float v[8] = {a.x, a.y, a.z, a.w, b.x, b.y, b.z, b.w};
    unsigned short h[24];
#pragma unroll
    for (int e = 0; e < 8; e++) {
        __nv_bfloat16 hi = __float2bfloat16(v[e]);
        __nv_bfloat16 lo = __float2bfloat16(v[e] - __bfloat162float(hi));
        unsigned short hb = __bfloat16_as_ushort(hi);
        unsigned short lb = __bfloat16_as_ushort(lo);
        h[3 * e] = hb;
        h[3 * e + 1] = mode ? lb : hb;
        h[3 * e + 2] = mode ? hb : lb;
    }
    uint4 w0, w1, w2;
    w0.x = h[0]  | (uint32_t)h[1]  << 16; w0.y = h[2]  | (uint32_t)h[3]  << 16;
    w0.z = h[4]  | (uint32_t)h[5]  << 16; w0.w = h[6]  | (uint32_t)h[7]  << 16;
    w1.x = h[8]  | (uint32_t)h[9]  << 16; w1.y = h[10] | (uint32_t)h[11] << 16;
    w1.z = h[12] | (uint32_t)h[13] << 16; w1.w = h[14] | (uint32_t)h[15] << 16;
    w2.x = h[16] | (uint32_t)h[17] << 16; w2.y = h[18] | (uint32_t)h[19] << 16;
    w2.z = h[20] | (uint32_t)h[21] << 16; w2.w = h[22] | (uint32_t)h[23] << 16;
    uint4* d4 = (uint4*)((char*)dst + t * 48);
    d4[0] = w0; d4[1] = w1; d4[2] = w2;
}

// =====================================================================
// Tiled causal conv1d (width 4) + bias + SiLU over xBC slice of proj.
// =====================================================================
__global__ __launch_bounds__(256) void conv_silu_tiled(const float* __restrict__ conv_w,
                                                       const float* __restrict__ conv_b) {
    __shared__ float xs[67][128];
    __shared__ float ws[128][4];
    __shared__ float bs[128];

    const int tid = threadIdx.x;
    const int b   = blockIdx.x >> 5;
    const int l0  = (blockIdx.x & 31) * 64;
    const int c0  = blockIdx.y * 128;

    if (tid < 128) {
        float4 w4 = *(const float4*)(conv_w + (size_t)(c0 + tid) * 4);
        ws[tid][0] = w4.x; ws[tid][1] = w4.y; ws[tid][2] = w4.z; ws[tid][3] = w4.w;
        bs[tid] = conv_b[c0 + tid];
    }

    for (int idx = tid; idx < 67 * 32; idx += 256) {
        int row = idx >> 5, c4 = (idx & 31) * 4;
        int l = l0 - 3 + row;
        float4 v = make_float4(0.f, 0.f, 0.f, 0.f);
        if (l >= 0)
            v = *(const float4*)(g_proj + (size_t)(b * SEQLEN + l) * DINPROJ + DINNER + c0 + c4);
        *(float4*)&xs[row][c4] = v;
    }
    __syncthreads();

    for (int idx = tid; idx < 64 * 32; idx += 256) {
        int row = idx >> 5, c4 = (idx & 31) * 4;
        float o[4];
#pragma unroll
        for (int e = 0; e < 4; e++) {
            int c = c4 + e;
            float acc = bs[c];
#pragma unroll
            for (int k = 0; k < 4; k++)
                acc = fmaf(xs[row + k][c], ws[c][k], acc);
            o[e] = acc * (1.f / (1.f + __expf(-acc)));
        }
        *(float4*)(g_xc + (size_t)(b * SEQLEN + l0 + row) * CONVDIM + c0 + c4) =
            make_float4(o[0], o[1], o[2], o[3]);
    }
}

// =====================================================================
// dt = softplus(sum of split-K partials + bias); cumsum(dA) per chunk
// =====================================================================
__global__ __launch_bounds__(256) void dt_scan(const float* __restrict__ A_log,
                                               const float* __restrict__ dt_bias) {
    const int bx = blockIdx.x;
    const int h  = bx & 31;
    const int q  = threadIdx.x;
    const int c  = (bx >> 5) & 7;
    const int b  = bx >> 8;
    const int bl = b * SEQLEN + c * CHUNK + q;

    float v = dt_bias[h];
#pragma unroll
    for (int s = 0; s < 8; s++) v += g_dtraw8[s][(size_t)bl * NHEADS + h];
    float dt = (v > 20.f) ? v : log1pf(__expf(v));
    g_dt[(size_t)bl * NHEADS + h] = dt;
    float dA = dt * (-__expf(A_log[h]));

    const int lane = q & 31, warp = q >> 5;
    float sv = dA;
#pragma unroll
    for (int off = 1; off < 32; off <<= 1) {
        float t = __shfl_up_sync(0xFFFFFFFFu, sv, off);
        if (lane >= off) sv += t;
    }
    __shared__ float wsum[8];
    if (lane == 31) wsum[warp] = sv;
    __syncthreads();
    float add = 0.f;
#pragma unroll
    for (int w = 0; w < 8; w++)
        if (w < warp) add += wsum[w];
    g_Acs[(size_t)bx * CHUNK + q] = sv + add;
}

// =====================================================================
// G[b,c,q,k] = sum_n C[q,n] * B[k,n]  — triangular grid: 10 tiles only
// =====================================================================
__constant__ int c_qt10[10] = {0, 1, 1, 2, 2, 2, 3, 3, 3, 3};
__constant__ int c_kt10[10] = {0, 0, 1, 0, 1, 2, 0, 1, 2, 3};

__global__ __launch_bounds__(256) void compute_G() {
    const int bc = blockIdx.x;
    const int q0 = c_qt10[blockIdx.y] * 64;
    const int k0 = c_kt10[blockIdx.y] * 64;

    __shared__ float Cs[64][65];
    __shared__ float Bs[64][65];
    const int tid = threadIdx.x;
    const int bl0 = (bc >> 3) * SEQLEN + (bc & 7) * CHUNK;

#pragma unroll
    for (int r = 0; r < 16; r++) {
        int idx = tid + r * 256;
        int row = idx >> 6, col = idx & 63;
        Cs[row][col] = g_xc[(size_t)(bl0 + q0 + row) * CONVDIM + DINNER + DSTATE + col];
        Bs[row][col] = g_xc[(size_t)(bl0 + k0 + row) * CONVDIM + DINNER + col];
    }
    __syncthreads();

    const int tx = tid & 15, ty = tid >> 4;
    float acc[4][4];
#pragma unroll
    for (int i = 0; i < 4; i++)
#pragma unroll
        for (int j = 0; j < 4; j++) acc[i][j] = 0.f;

    for (int n = 0; n < 64; n++) {
        float a[4], b[4];
#pragma unroll
        for (int i = 0; i < 4; i++) a[i] = Cs[ty * 4 + i][n];
#pragma unroll
        for (int j = 0; j < 4; j++) b[j] = Bs[tx * 4 + j][n];
#pragma unroll
        for (int i = 0; i < 4; i++)
#pragma unroll
            for (int j = 0; j < 4; j++) acc[i][j] = fmaf(a[i], b[j], acc[i][j]);
    }
#pragma unroll
    for (int i = 0; i < 4; i++)
#pragma unroll
        for (int j = 0; j < 4; j++)
            g_G[((size_t)bc * CHUNK + q0 + ty * 4 + i) * CHUNK + k0 + tx * 4 + j] = acc[i][j];
}

// =====================================================================
// states: per-chunk B^T (decay * x*dt)   [256-thread proven version]
// =====================================================================
__global__ __launch_bounds__(256) void compute_states() {
    const int bx = blockIdx.x;
    const int h  = bx & 31;
    const int c  = (bx >> 5) & 7;
    const int b  = bx >> 8;
    const int bl0 = b * SEQLEN + c * CHUNK;

    float* Acs_s = smem_dyn;
    float* dt_s  = smem_dyn + 256;
    float* Bs    = smem_dyn + 512;
    float* Xs    = Bs + 64 * 65;

    const int tid = threadIdx.x;
    Acs_s[tid] = g_Acs[(size_t)bx * CHUNK + tid];
    dt_s[tid]  = g_dt[(size_t)(bl0 + tid) * NHEADS + h];
    __syncthreads();
    const float Alast = Acs_s[255];

    const int tx = tid & 15, ty = tid >> 4;
    float acc[4][8];
#pragma unroll
    for (int i = 0; i < 4; i++)
#pragma unroll
        for (int j = 0; j < 8; j++) acc[i][j] = 0.f;

    for (int kt = 0; kt < 4; kt++) {
        const int k0 = kt * 64;
        __syncthreads();
#pragma unroll
        for (int r = 0; r < 16; r++) {
            int idx = tid + r * 256;
            int kk = idx >> 6, n = idx & 63;
            float dec = __expf(Alast - Acs_s[k0 + kk]);
            Bs[kk * 65 + n] = g_xc[(size_t)(bl0 + k0 + kk) * CONVDIM + DINNER + n] * dec;
        }
#pragma unroll
        for (int r = 0; r < 8; r++) {
            int f4 = tid + r * 256;
            int kk = f4 >> 5, p4 = f4 & 31;
            float4 v = *(const float4*)(g_xc + (size_t)(bl0 + k0 + kk) * CONVDIM + h * HEADDIM + p4 * 4);
            float d = dt_s[k0 + kk];
            v.x *= d; v.y *= d; v.z *= d; v.w *= d;
            *(float4*)(Xs + kk * 128 + p4 * 4) = v;
        }
        __syncthreads();
        for (int kk = 0; kk < 64; kk++) {
            float a[4], bb[8];
#pragma unroll
            for (int i = 0; i < 4; i++) a[i] = Bs[kk * 65 + ty * 4 + i];
            *(float4*)&bb[0] = *(const float4*)(Xs + kk * 128 + tx * 8);
            *(float4*)&bb[4] = *(const float4*)(Xs + kk * 128 + tx * 8 + 4);
#pragma unroll
            for (int i = 0; i < 4; i++)
#pragma unroll
                for (int j = 0; j < 8; j++) acc[i][j] = fmaf(a[i], bb[j], acc[i][j]);
        }
    }

    size_t base = (size_t)bx * (DSTATE * HEADDIM);
#pragma unroll
    for (int i = 0; i < 4; i++) {
        int n = ty * 4 + i;
#pragma unroll
        for (int j = 0; j < 8; j += 4) {
            float4 v = make_float4(acc[i][j], acc[i][j + 1], acc[i][j + 2], acc[i][j + 3]);
            *(float4*)(g_states + base + (size_t)n * 128 + tx * 8 + j) = v;
        }
    }
}

// =====================================================================
// inter-chunk scan
// =====================================================================
__global__ __launch_bounds__(256) void chunk_scan() {
    const int bh = blockIdx.x;
    const int b = bh >> 5, h = bh & 31;
    __shared__ float cd[NCHUNK];
    if (threadIdx.x < NCHUNK) {
        int c = threadIdx.x;
        cd[c] = __expf(g_Acs[(size_t)(((b * 8 + c) * 32) + h) * CHUNK + 255]);
    }
    __syncthreads();
    for (int e = threadIdx.x; e < DSTATE * HEADDIM; e += 256) {
        float carry = 0.f;
#pragma unroll
        for (int c = 0; c < NCHUNK; c++) {
            size_t idx = (size_t)(((b * 8 + c) * 32) + h) * (DSTATE * HEADDIM) + e;
            g_prev[idx] = carry;
            carry = carry * cd[c] + g_states[idx];
        }
    }
}

// =====================================================================
// Y = diag + off + x*D   [256-thread proven version; off-diag unguarded]
// =====================================================================
__global__ __launch_bounds__(256) void compute_Y(const float* __restrict__ Dp) {
    const int bx = blockIdx.x;
    const int h  = bx & 31;
    const int bc = bx >> 5;
    const int c  = bc & 7;
    const int b  = bc >> 3;
    const int bl0 = b * SEQLEN + c * CHUNK;

    float* Acs_s = smem_dyn;
    float* dt_s  = smem_dyn + 256;
    float* Ws    = smem_dyn + 512;
    float* Xs    = Ws + 64 * 65;

    const int tid = threadIdx.x;
    Acs_s[tid] = g_Acs[(size_t)bx * CHUNK + tid];
    dt_s[tid]  = g_dt[(size_t)(bl0 + tid) * NHEADS + h];
    __syncthreads();

    const int tx = tid & 15, ty = tid >> 4;
    const float Dh = Dp[h];

    for (int qt = 0; qt < 4; qt++) {
        const int q0 = qt * 64;
        float acc[4][8];
#pragma unroll
        for (int i = 0; i < 4; i++)
#pragma unroll
            for (int j = 0; j < 8; j++) acc[i][j] = 0.f;

        for (int kt = 0; kt <= qt; kt++) {
            const int k0 = kt * 64;
            __syncthreads();
            if (kt < qt) {
#pragma unroll
                for (int r = 0; r < 16; r++) {
                    int idx = tid + r * 256;
                    int qq = idx >> 6, kk = idx & 63;
                    int q = q0 + qq, k = k0 + kk;
                    Ws[qq * 65 + kk] = g_G[((size_t)bc * CHUNK + q) * CHUNK + k]
                                       * __expf(Acs_s[q] - Acs_s[k]);
                }
            } else {
#pragma unroll
                for (int r = 0; r < 16; r++) {
                    int idx = tid + r * 256;
                    int qq = idx >> 6, kk = idx & 63;
                    int q = q0 + qq, k = k0 + kk;
                    float w = 0.f;
                    if (k <= q)
                        w = g_G[((size_t)bc * CHUNK + q) * CHUNK + k]
                            * __expf(Acs_s[q] - Acs_s[k]);
                    Ws[qq * 65 + kk] = w;
                }
            }
#pragma unroll
            for (int r = 0; r < 8; r++) {
                int f4 = tid + r * 256;
                int kk = f4 >> 5, p4 = f4 & 31;
                float4 v = *(const float4*)(g_xc + (size_t)(bl0 + k0 + kk) * CONVDIM + h * HEADDIM + p4 * 4);
                float d = dt_s[k0 + kk];
                v.x *= d; v.y *= d; v.z *= d; v.w *= d;
                *(float4*)(Xs + kk * 128 + p4 * 4) = v;
            }
            __syncthreads();
            for (int kk = 0; kk < 64; kk++) {
                float a[4], bb[8];
#pragma unroll
                for (int i = 0; i < 4; i++) a[i] = Ws[(ty * 4 + i) * 65 + kk];
                *(float4*)&bb[0] = *(const float4*)(Xs + kk * 128 + tx * 8);
                *(float4*)&bb[4] = *(const float4*)(Xs + kk * 128 + tx * 8 + 4);
#pragma unroll
                for (int i = 0; i < 4; i++)
#pragma unroll
                    for (int j = 0; j < 8; j++) acc[i][j] = fmaf(a[i], bb[j], acc[i][j]);
            }
        }

        // ---- Y_off: (C * e^{Acs_q}) @ prev ----
        __syncthreads();
#pragma unroll
        for (int r = 0; r < 16; r++) {
            int idx = tid + r * 256;
            int qq = idx >> 6, n = idx & 63;
            Ws[qq * 65 + n] = g_xc[(size_t)(bl0 + q0 + qq) * CONVDIM + DINNER + DSTATE + n]
                              * __expf(Acs_s[q0 + qq]);
        }
#pragma unroll
        for (int r = 0; r < 8; r++) {
            int f4 = tid + r * 256;
            int n = f4 >> 5, p4 = f4 & 31;
            *(float4*)(Xs + n * 128 + p4 * 4) =
                *(const float4*)(g_prev + (size_t)bx * (DSTATE * HEADDIM) + (size_t)n * 128 + p4 * 4);
        }
        __syncthreads();
        for (int n = 0; n < 64; n++) {
            float a[4], bb[8];
#pragma unroll
            for (int i = 0; i < 4; i++) a[i] = Ws[(ty * 4 + i) * 65 + n];
            *(float4*)&bb[0] = *(const float4*)(Xs + n * 128 + tx * 8);
            *(float4*)&bb[4] = *(const float4*)(Xs + n * 128 + tx * 8 + 4);
#pragma unroll
            for (int i = 0; i < 4; i++)
#pragma unroll
                for (int j = 0; j < 8; j++) acc[i][j] = fmaf(a[i], bb[j], acc[i][j]);
        }

#pragma unroll
        for (int i = 0; i < 4; i++) {
            int q = q0 + ty * 4 + i;
            const float* xr = g_xc + (size_t)(bl0 + q) * CONVDIM + h * HEADDIM + tx * 8;
            float* yr = g_y + (size_t)(bl0 + q) * DINNER + h * HEADDIM + tx * 8;
#pragma unroll
            for (int j = 0; j < 8; j++) yr[j] = acc[i][j] + xr[j] * Dh;
        }
    }
}

// =====================================================================
// RMSNorm + SiLU gate + split3(mode 0), single pass over y (registers)
// =====================================================================
__global__ __launch_bounds__(256) void rmsnorm_gate_split() {
    const int bl = blockIdx.x;
    const float* y = g_y + (size_t)bl * DINNER;
    const float* z = g_proj + (size_t)bl * DINPROJ;
    const int t = threadIdx.x;

    // load 16 y-values into registers (single read of g_y)
    float yy[16];
    const float4* y4 = (const float4*)(y + t * 16);
    *(float4*)&yy[0]  = y4[0];
    *(float4*)&yy[4]  = y4[1];
    *(float4*)&yy[8]  = y4[2];
    *(float4*)&yy[12] = y4[3];

    float ss = 0.f;
#pragma unroll
    for (int e = 0; e < 16; e++) ss += yy[e] * yy[e];

    __shared__ float red[256];
    red[t] = ss;
    __syncthreads();
    for (int s = 128; s > 0; s >>= 1) {
        if (t < s) red[t] += red[t + s];
        __syncthreads();
    }
    float r = rsqrtf(red[0] / (float)DINNER + EPSF);

#pragma unroll
    for (int gb = 0; gb < 2; gb++) {
        const int base = t * 16 + gb * 8;
        float4 z0 = *(const float4*)(z + base);
        float4 z1 = *(const float4*)(z + base + 4);
        float zz[8] = {z0.x, z0.y, z0.z, z0.w, z1.x, z1.y, z1.z, z1.w};
        float v[8];
#pragma unroll
        for (int e = 0; e < 8; e++)
            v[e] = yy[gb * 8 + e] * r * (zz[e] / (1.f + __expf(-zz[e])));
        unsigned short h[24];
#pragma unroll
        for (int e = 0; e < 8; e++) {
            __nv_bfloat16 hi = __float2bfloat16(v[e]);
            __nv_bfloat16 lo = __float2bfloat16(v[e] - __bfloat162float(hi));
            unsigned short hb = __bfloat16_as_ushort(hi);
            unsigned short lb = __bfloat16_as_ushort(lo);
            h[3 * e] = hb; h[3 * e + 1] = hb; h[3 * e + 2] = lb;
        }
        uint4 w0, w1, w2;
        w0.x = h[0]  | (uint32_t)h[1]  << 16; w0.y = h[2]  | (uint32_t)h[3]  << 16;
        w0.z = h[4]  | (uint32_t)h[5]  << 16; w0.w = h[6]  | (uint32_t)h[7]  << 16;
        w1.x = h[8]  | (uint32_t)h[9]  << 16; w1.y = h[10] | (uint32_t)h[11] << 16;
        w1.z = h[12] | (uint32_t)h[13] << 16; w1.w = h[14] | (uint32_t)h[15] << 16;
        w2.x = h[16] | (uint32_t)h[17] << 16; w2.y = h[18] | (uint32_t)h[19] << 16;
        w2.z = h[20] | (uint32_t)h[21] << 16; w2.w = h[22] | (uint32_t)h[23] << 16;
        uint4* d4 = (uint4*)((char*)g_g3 + ((size_t)bl * K3_OUT + 3 * (size_t)base) * 2);
        d4[0] = w0; d4[1] = w1; d4[2] = w2;
    }
}

// =====================================================================
// launch
// =====================================================================
extern "C" void kernel_launch(void* const* d_in, const int* in_sizes, int n_in,
                              void* d_out, int out_size) {
    const float* x       = (const float*)d_in[0];
    const float* W_in    = (const float*)d_in[1];
    const float* conv_w  = (const float*)d_in[2];
    const float* conv_b  = (const float*)d_in[3];
    const float* A_log   = (const float*)d_in[4];
    const float* dt_bias = (const float*)d_in[5];
    const float* Dp      = (const float*)d_in[6];
    const float* W_out   = (const float*)d_in[7];
    float* out = (float*)d_out;

    float *p_proj = nullptr;
    __nv_bfloat16 *p_x3, *p_w3, *p_g3, *p_wo3;
    cudaGetSymbolAddress((void**)&p_proj, g_proj);
    cudaGetSymbolAddress((void**)&p_x3, g_x3);
    cudaGetSymbolAddress((void**)&p_w3, g_w3);
    cudaGetSymbolAddress((void**)&p_g3, g_g3);
    cudaGetSymbolAddress((void**)&p_wo3, g_wo3);

    const int SMEM_DYN = (512 + 64 * 65 + 64 * 128) * 4;   // 51456
    cudaFuncSetAttribute((const void*)compute_states,
                         cudaFuncAttributeMaxDynamicSharedMemorySize, SMEM_DYN);
    cudaFuncSetAttribute((const void*)compute_Y,
                         cudaFuncAttributeMaxDynamicSharedMemorySize, SMEM_DYN);
    cudaFuncSetAttribute((const void*)gemm_mma,
                         cudaFuncAttributeMaxDynamicSharedMemorySize, GEMM_SMEM);

    // --- split operands for GEMM1 ---
    split3<<<(unsigned)(((size_t)BL * DMODEL / 8 + 255) / 256), 256>>>(x, p_x3, (size_t)BL * DMODEL / 8, 0);
    {
        size_t halfRows = DINPROJ / 2;                       // 4176
        size_t n8 = halfRows * DMODEL / 8;
        split3<<<(unsigned)((n8 + 255) / 256), 256>>>(W_in, p_w3, n8, 1);
        split3<<<(unsigned)((n8 + 255) / 256), 256>>>(W_in + halfRows * DMODEL,
                                                      p_w3 + halfRows * K3_IN, n8, 1);
    }

    // --- GEMM1 (tensor cores): proj = x @ W_in^T ---
    {
        int tilesN = (DINPROJ + 127) / 128;   // 66
        int tilesM = BL / 128;                // 64
        gemm_mma<<<tilesM * tilesN, 128, GEMM_SMEM>>>(
            p_x3, p_w3, p_proj, BL, DINPROJ, K3_IN, tilesN);
    }

    // --- dt repair GEMM (exact fp32, split-K x 8) ---
    gemm_dt<<<dim3(BL / 32, 8), 256>>>(x, W_in + (size_t)(DINNER + CONVDIM) * DMODEL);

    // --- conv + silu (tiled, read-once) ---
    conv_silu_tiled<<<dim3(BATCH * (SEQLEN / 64), CONVDIM / 128), 256>>>(conv_w, conv_b);

    // --- dt, cumsum(dA) ---
    dt_scan<<<BATCH * NCHUNK * NHEADS, 256>>>(A_log, dt_bias);

    // --- SSD ---
    compute_G<<<dim3(BATCH * NCHUNK, 10), 256>>>();
    compute_states<<<BATCH * NCHUNK * NHEADS, 256, SMEM_DYN>>>();
    chunk_scan<<<BATCH * NHEADS, 256>>>();
    compute_Y<<<BATCH * NCHUNK * NHEADS, 256, SMEM_DYN>>>(Dp);

    // --- rmsnorm + gate + split (fused, single-pass) ---
    rmsnorm_gate_split<<<BL, 256>>>();

    // --- split weights for GEMM2 ---
    split3<<<(unsigned)(((size_t)DMODEL * DINNER / 8 + 255) / 256), 256>>>(W_out, p_wo3, (size_t)DMODEL * DINNER / 8, 1);

    // --- GEMM2 (tensor cores): out = gated @ W_out^T ---
    {
        int tilesN = DMODEL / 128;            // 16
        int tilesM = BL / 128;                // 64
        gemm_mma<<<tilesM * tilesN, 128, GEMM_SMEM>>>(
            p_g3, p_wo3, out, BL, DMODEL, K3_OUT, tilesN);
    }
}

// round 17
// speedup vs baseline: 1.0592x; 1.0217x over previous
#include <cuda_runtime.h>
#include <cuda_bf16.h>
#include <cstdint>
#include <cstddef>

// ---------------- problem constants ----------------
#define BATCH   4
#define SEQLEN  2048
#define DMODEL  2048
#define DINNER  4096
#define DSTATE  64
#define NHEADS  32
#define HEADDIM 128
#define CHUNK   256
#define NCHUNK  8
#define CONVDIM (DINNER + 2*DSTATE)           // 4224
#define DINPROJ (DINNER + CONVDIM + NHEADS)   // 8352
#define NPROJ_TC (DINNER + CONVDIM)           // 8320 = 65*128 (dt cols dropped)
#define BL      (BATCH*SEQLEN)                // 8192
#define EPSF    1.1920929e-07f

#define K3_IN   (3*DMODEL)                    // 6144
#define K3_OUT  (3*DINNER)                    // 12288

// ---------------- device scratch ----------------
__device__ float g_proj  [(size_t)BL * DINPROJ];
__device__ float g_xc    [(size_t)BL * CONVDIM];
__device__ float g_dt    [(size_t)BL * NHEADS];
__device__ float g_dtraw8[8][(size_t)BL * NHEADS];
__device__ float g_Acs   [(size_t)BATCH*NCHUNK*NHEADS*CHUNK];
__device__ float g_G     [(size_t)BATCH*NCHUNK*CHUNK*CHUNK];
__device__ float g_states[(size_t)BATCH*NCHUNK*NHEADS*DSTATE*HEADDIM];
__device__ float g_prev  [(size_t)BATCH*NCHUNK*NHEADS*DSTATE*HEADDIM];
__device__ float g_y     [(size_t)BL * DINNER];
// bf16 split-interleaved operands
__device__ __align__(16) __nv_bfloat16 g_x3 [(size_t)BL * K3_IN];       // (hi,hi,lo)
__device__ __align__(16) __nv_bfloat16 g_w3 [(size_t)DINPROJ * K3_IN];  // (hi,lo,hi)
__device__ __align__(16) __nv_bfloat16 g_g3 [(size_t)BL * K3_OUT];      // (hi,hi,lo)
__device__ __align__(16) __nv_bfloat16 g_wo3[(size_t)DMODEL * K3_OUT];  // (hi,lo,hi)

extern __shared__ float smem_dyn[];

// =====================================================================
// helpers
// =====================================================================
__device__ __forceinline__ uint32_t cvta_s(const void* p) {
    return (uint32_t)__cvta_generic_to_shared(p);
}
__device__ __forceinline__ void cp_async16(uint32_t dst, const void* src, uint32_t sz) {
    asm volatile("cp.async.cg.shared.global [%0], [%1], 16, %2;"
                 :: "r"(dst), "l"(src), "r"(sz) : "memory");
}
__device__ __forceinline__ void cp_commit() {
    asm volatile("cp.async.commit_group;" ::: "memory");
}
template <int N>
__device__ __forceinline__ void cp_wait() {
    asm volatile("cp.async.wait_group %0;" :: "n"(N) : "memory");
}
__device__ __forceinline__ void mma16816(float* c, const uint32_t* a, const uint32_t* b) {
    asm volatile(
        "mma.sync.aligned.m16n8k16.row.col.f32.bf16.bf16.f32 "
        "{%0,%1,%2,%3}, {%4,%5,%6,%7}, {%8,%9}, {%0,%1,%2,%3};"
        : "+f"(c[0]), "+f"(c[1]), "+f"(c[2]), "+f"(c[3])
        : "r"(a[0]), "r"(a[1]), "r"(a[2]), "r"(a[3]), "r"(b[0]), "r"(b[1]));
}
__device__ __forceinline__ void ldsm_x4(uint32_t* r, uint32_t addr) {
    asm volatile("ldmatrix.sync.aligned.m8n8.x4.shared.b16 {%0,%1,%2,%3}, [%4];"
                 : "=r"(r[0]), "=r"(r[1]), "=r"(r[2]), "=r"(r[3]) : "r"(addr));
}
__device__ __forceinline__ void split2(float v, __nv_bfloat16* hp, __nv_bfloat16* lp) {
    __nv_bfloat16 hi = __float2bfloat16(v);
    *hp = hi;
    *lp = __float2bfloat16(v - __bfloat162float(hi));
}

// =====================================================================
// mma.sync bf16 GEMM-NT (R14/R16 winner): 128x128 tile, 128 threads,
// warp tile 64x64, K-chunk 64, 3-stage ring, 2 CTAs/SM.  Cld = C row
// stride (may exceed N).
// =====================================================================
#define MSTG      3
#define MKCH      64
#define ASTRIDE   72
#define OPA_ELEMS (128*ASTRIDE)
#define OPB_ELEMS (128*ASTRIDE)
#define STG_ELEMS (OPA_ELEMS+OPB_ELEMS)
#define GEMM_SMEM (MSTG*STG_ELEMS*2)        // 110592 bytes
#define SUPERM    8

__global__ __launch_bounds__(128, 2)
void gemm_mma(const __nv_bfloat16* __restrict__ A,
              const __nv_bfloat16* __restrict__ B,
              float* __restrict__ C,
              int M, int N, int K3, int tilesN, int Cld) {
    extern __shared__ __nv_bfloat16 sm[];
    const int tid  = threadIdx.x;
    const int lane = tid & 31;
    const int wid  = tid >> 5;

    const int lin = blockIdx.x;
    const int per = SUPERM * tilesN;
    const int grp = lin / per, rem = lin % per;
    const int m0 = (grp * SUPERM + (rem % SUPERM)) * 128;
    const int n0 = (rem / SUPERM) * 128;

    const int NK = K3 / MKCH;

    const int g  = lane >> 2;
    const int t2 = (lane & 3) * 2;
    const int wr0 = (wid & 1) * 64;
    const int wc0 = (wid >> 1) * 64;

    const uint32_t smBase = cvta_s(sm);

    const int aRow = ((lane >> 3) & 1) * 8 + (lane & 7);
    const int aK   = (lane >> 4) * 8;
    const int bRow = (lane >> 4) * 8 + (lane & 7);
    const int bK   = ((lane >> 3) & 1) * 8;

    auto load_stage = [&](int st, int i) {
        const size_t koff = (size_t)i * MKCH * 2;
        const uint32_t sb = smBase + (uint32_t)st * (STG_ELEMS * 2);
#pragma unroll
        for (int r = 0; r < 16; r++) {
            int idx = tid + r * 128;
            int isB = idx >= 1024;
            int li  = isB ? idx - 1024 : idx;
            int row = li >> 3, c = li & 7;
            uint32_t dst = sb + (uint32_t)isB * (OPA_ELEMS * 2) + row * (ASTRIDE * 2) + c * 16;
            const char* src;
            uint32_t sz = 16;
            if (!isB) {
                src = (const char*)A + ((size_t)(m0 + row) * K3) * 2 + koff + c * 16;
            } else {
                int rr = n0 + row;
                if (rr < N) src = (const char*)B + ((size_t)rr * K3) * 2 + koff + c * 16;
                else { src = (const char*)B; sz = 0; }
            }
            cp_async16(dst, src, sz);
        }
    };

    float acc[4][8][4];
#pragma unroll
    for (int mt = 0; mt < 4; mt++)
#pragma unroll
        for (int nt = 0; nt < 8; nt++)
#pragma unroll
            for (int e = 0; e < 4; e++) acc[mt][nt][e] = 0.f;

    load_stage(0, 0); cp_commit();
    load_stage(1, 1); cp_commit();
    load_stage(2, 2); cp_commit();

    uint32_t afr[2][4][4];
    uint32_t bfr[2][4][4];

    cp_wait<2>();
    __syncthreads();
    {
        const uint32_t sA = smBase;
        const uint32_t sB = sA + OPA_ELEMS * 2;
#pragma unroll
        for (int mt = 0; mt < 4; mt++)
            ldsm_x4(afr[0][mt], sA + ((wr0 + mt * 16 + aRow) * ASTRIDE + aK) * 2);
#pragma unroll
        for (int p = 0; p < 4; p++)
            ldsm_x4(bfr[0][p], sB + ((wc0 + p * 16 + bRow) * ASTRIDE + bK) * 2);
    }

    int slot = 0;
    for (int i = 0; i < NK; i++) {
        const int nslot = (slot + 1 == MSTG) ? 0 : slot + 1;
        const uint32_t sA = smBase + (uint32_t)slot * (STG_ELEMS * 2);
        const uint32_t sB = sA + OPA_ELEMS * 2;
        const uint32_t sAn = smBase + (uint32_t)nslot * (STG_ELEMS * 2);
        const uint32_t sBn = sAn + OPA_ELEMS * 2;

#pragma unroll
        for (int kg = 0; kg < 4; kg++) {
            const int buf = kg & 1;
            const int nb = buf ^ 1;
            if (kg < 3) {
                const int kb = (kg + 1) * 16;
#pragma unroll
                for (int mt = 0; mt < 4; mt++)
                    ldsm_x4(afr[nb][mt], sA + ((wr0 + mt * 16 + aRow) * ASTRIDE + kb + aK) * 2);
#pragma unroll
                for (int p = 0; p < 4; p++)
                    ldsm_x4(bfr[nb][p], sB + ((wc0 + p * 16 + bRow) * ASTRIDE + kb + bK) * 2);
            } else if (i + 1 < NK) {
                cp_wait<1>();
                __syncthreads();
                if (i + 3 < NK) load_stage(slot, i + 3);
#pragma unroll
                for (int mt = 0; mt < 4; mt++)
                    ldsm_x4(afr[nb][mt], sAn + ((wr0 + mt * 16 + aRow) * ASTRIDE + aK) * 2);
#pragma unroll
                for (int p = 0; p < 4; p++)
                    ldsm_x4(bfr[nb][p], sBn + ((wc0 + p * 16 + bRow) * ASTRIDE + bK) * 2);
            }
#pragma unroll
            for (int mt = 0; mt < 4; mt++)
#pragma unroll
                for (int nt = 0; nt < 8; nt++)
                    mma16816(acc[mt][nt], afr[buf][mt], &bfr[buf][nt >> 1][(nt & 1) * 2]);
        }
        cp_commit();
        slot = nslot;
    }

#pragma unroll
    for (int mt = 0; mt < 4; mt++) {
        int r0 = m0 + wr0 + mt * 16 + g;
#pragma unroll
        for (int nt = 0; nt < 8; nt++) {
            int cc = n0 + wc0 + nt * 8 + t2;
            if (cc + 1 < N) {
                *(float2*)(C + (size_t)r0 * Cld + cc) = make_float2(acc[mt][nt][0], acc[mt][nt][1]);
                *(float2*)(C + (size_t)(r0 + 8) * Cld + cc) = make_float2(acc[mt][nt][2], acc[mt][nt][3]);
            } else if (cc < N) {
                C[(size_t)r0 * Cld + cc] = acc[mt][nt][0];
                C[(size_t)(r0 + 8) * Cld + cc] = acc[mt][nt][2];
            }
        }
    }
}

// =====================================================================
// skinny fp32 GEMM for dt repair, split-K x 8.
// =====================================================================
__global__ __launch_bounds__(256) void gemm_dt(const float* __restrict__ x,
                                               const float* __restrict__ W) {
    __shared__ float xs[32][33];
    __shared__ float Wt[32][33];
    const int t = threadIdx.x;
    const int rc = t >> 3;
    const int k4 = (t & 7) * 4;
    const int w = t >> 5, l = t & 31;
    const int row0 = blockIdx.x * 32;
    const int s = blockIdx.y;
    const int kbeg = s * (DMODEL / 8);

    float acc[4] = {0.f, 0.f, 0.f, 0.f};
    for (int k0 = kbeg; k0 < kbeg + DMODEL / 8; k0 += 32) {
        __syncthreads();
        float4 xv = *(const float4*)(x + (size_t)(row0 + rc) * DMODEL + k0 + k4);
        xs[rc][k4 + 0] = xv.x; xs[rc][k4 + 1] = xv.y;
        xs[rc][k4 + 2] = xv.z; xs[rc][k4 + 3] = xv.w;
        float4 wv = *(const float4*)(W + (size_t)rc * DMODEL + k0 + k4);
        Wt[k4 + 0][rc] = wv.x; Wt[k4 + 1][rc] = wv.y;
        Wt[k4 + 2][rc] = wv.z; Wt[k4 + 3][rc] = wv.w;
        __syncthreads();
#pragma unroll
        for (int kk = 0; kk < 32; kk++) {
            float wl = Wt[kk][l];
#pragma unroll
            for (int r = 0; r < 4; r++)
                acc[r] = fmaf(xs[w * 4 + r][kk], wl, acc[r]);
        }
    }
#pragma unroll
    for (int r = 0; r < 4; r++)
        g_dtraw8[s][(size_t)(row0 + w * 4 + r) * NHEADS + l] = acc[r];
}

// =====================================================================
// split3: fp32 -> interleaved bf16 triples. mode 0: (hi,hi,lo), 1: (hi,lo,hi)
// =====================================================================
__global__ __launch_bounds__(256) void split3(const float* __restrict__ src,
                                              __nv_bfloat16* __restrict__ dst,
                                              size_t n8, int mode) {
    size_t t = (size_t)blockIdx.x * blockDim.x + threadIdx.x;
    if (t >= n8) return;
    const float4* s4 = (const float4*)(src + t * 8);
    float4 a = s4[0], b = s4[1];
    float v[8] = {a.x, a.y, a.z, a.w, b.x, b.y, b.z, b.w};
    unsigned short h[24];
#pragma unroll
    for (int e = 0; e < 8; e++) {
        __nv_bfloat16 hi = __float2bfloat16(v[e]);
        __nv_bfloat16 lo = __float2bfloat16(v[e] - __bfloat162float(hi));
        unsigned short hb = __bfloat16_as_ushort(hi);
        unsigned short lb = __bfloat16_as_ushort(lo);
        h[3 * e] = hb;
        h[3 * e + 1] = mode ? lb : hb;
        h[3 * e + 2] = mode ? hb : lb;
    }
    uint4 w0, w1, w2;
    w0.x = h[0]  | (uint32_t)h[1]  << 16; w0.y = h[2]  | (uint32_t)h[3]  << 16;
    w0.z = h[4]  | (uint32_t)h[5]  << 16; w0.w = h[6]  | (uint32_t)h[7]  << 16;
    w1.x = h[8]  | (uint32_t)h[9]  << 16; w1.y = h[10] | (uint32_t)h[11] << 16;
    w1.z = h[12] | (uint32_t)h[13] << 16; w1.w = h[14] | (uint32_t)h[15] << 16;
    w2.x = h[16] | (uint32_t)h[17] << 16; w2.y = h[18] | (uint32_t)h[19] << 16;
    w2.z = h[20] | (uint32_t)h[21] << 16; w2.w = h[22] | (uint32_t)h[23] << 16;
    uint4* d4 = (uint4*)((char*)dst + t * 48);
    d4[0] = w0; d4[1] = w1; d4[2] = w2;
}

// =====================================================================
// Tiled causal conv1d (width 4) + bias + SiLU over xBC slice of proj.
// =====================================================================
__global__ __launch_bounds__(256) void conv_silu_tiled(const float* __restrict__ conv_w,
                                                       const float* __restrict__ conv_b) {
    __shared__ float xs[67][128];
    __shared__ float ws[128][4];
    __shared__ float bs[128];

    const int tid = threadIdx.x;
    const int b   = blockIdx.x >> 5;
    const int l0  = (blockIdx.x & 31) * 64;
    const int c0  = blockIdx.y * 128;

    if (tid < 128) {
        float4 w4 = *(const float4*)(conv_w + (size_t)(c0 + tid) * 4);
        ws[tid][0] = w4.x; ws[tid][1] = w4.y; ws[tid][2] = w4.z; ws[tid][3] = w4.w;
        bs[tid] = conv_b[c0 + tid];
    }

    for (int idx = tid; idx < 67 * 32; idx += 256) {
        int row = idx >> 5, c4 = (idx & 31) * 4;
        int l = l0 - 3 + row;
        float4 v = make_float4(0.f, 0.f, 0.f, 0.f);
        if (l >= 0)
            v = *(const float4*)(g_proj + (size_t)(b * SEQLEN + l) * DINPROJ + DINNER + c0 + c4);
        *(float4*)&xs[row][c4] = v;
    }
    __syncthreads();

    for (int idx = tid; idx < 64 * 32; idx += 256) {
        int row = idx >> 5, c4 = (idx & 31) * 4;
        float o[4];
#pragma unroll
        for (int e = 0; e < 4; e++) {
            int c = c4 + e;
            float acc = bs[c];
#pragma unroll
            for (int k = 0; k < 4; k++)
                acc = fmaf(xs[row + k][c], ws[c][k], acc);
            o[e] = acc * (1.f / (1.f + __expf(-acc)));
        }
        *(float4*)(g_xc + (size_t)(b * SEQLEN + l0 + row) * CONVDIM + c0 + c4) =
            make_float4(o[0], o[1], o[2], o[3]);
    }
}

// =====================================================================
// dt = softplus(sum of split-K partials + bias); cumsum(dA) per chunk
// =====================================================================
__global__ __launch_bounds__(256) void dt_scan(const float* __restrict__ A_log,
                                               const float* __restrict__ dt_bias) {
    const int bx = blockIdx.x;
    const int h  = bx & 31;
    const int q  = threadIdx.x;
    const int c  = (bx >> 5) & 7;
    const int b  = bx >> 8;
    const int bl = b * SEQLEN + c * CHUNK + q;

    float v = dt_bias[h];
#pragma unroll
    for (int s = 0; s < 8; s++) v += g_dtraw8[s][(size_t)bl * NHEADS + h];
    float dt = (v > 20.f) ? v : log1pf(__expf(v));
    g_dt[(size_t)bl * NHEADS + h] = dt;
    float dA = dt * (-__expf(A_log[h]));

    const int lane = q & 31, warp = q >> 5;
    float sv = dA;
#pragma unroll
    for (int off = 1; off < 32; off <<= 1) {
        float t = __shfl_up_sync(0xFFFFFFFFu, sv, off);
        if (lane >= off) sv += t;
    }
    __shared__ float wsum[8];
    if (lane == 31) wsum[warp] = sv;
    __syncthreads();
    float add = 0.f;
#pragma unroll
    for (int w = 0; w < 8; w++)
        if (w < warp) add += wsum[w];
    g_Acs[(size_t)bx * CHUNK + q] = sv + add;
}

// =====================================================================
// G[b,c,q,k] = sum_n C[q,n] * B[k,n]  — triangular grid: 10 tiles only
// =====================================================================
__constant__ int c_qt10[10] = {0, 1, 1, 2, 2, 2, 3, 3, 3, 3};
__constant__ int c_kt10[10] = {0, 0, 1, 0, 1, 2, 0, 1, 2, 3};

__global__ __launch_bounds__(256) void compute_G() {
    const int bc = blockIdx.x;
    const int q0 = c_qt10[blockIdx.y] * 64;
    const int k0 = c_kt10[blockIdx.y] * 64;

    __shared__ float Cs[64][65];
    __shared__ float Bs[64][65];
    const int tid = threadIdx.x;
    const int bl0 = (bc >> 3) * SEQLEN + (bc & 7) * CHUNK;

#pragma unroll
    for (int r = 0; r < 16; r++) {
        int idx = tid + r * 256;
        int row = idx >> 6, col = idx & 63;
        Cs[row][col] = g_xc[(size_t)(bl0 + q0 + row) * CONVDIM + DINNER + DSTATE + col];
        Bs[row][col] = g_xc[(size_t)(bl0 + k0 + row) * CONVDIM + DINNER + col];
    }
    __syncthreads();

    const int tx = tid & 15, ty = tid >> 4;
    float acc[4][4];
#pragma unroll
    for (int i = 0; i < 4; i++)
#pragma unroll
        for (int j = 0; j < 4; j++) acc[i][j] = 0.f;

    for (int n = 0; n < 64; n++) {
        float a[4], b[4];
#pragma unroll
        for (int i = 0; i < 4; i++) a[i] = Cs[ty * 4 + i][n];
#pragma unroll
        for (int j = 0; j < 4; j++) b[j] = Bs[tx * 4 + j][n];
#pragma unroll
        for (int i = 0; i < 4; i++)
#pragma unroll
            for (int j = 0; j < 4; j++) acc[i][j] = fmaf(a[i], b[j], acc[i][j]);
    }
#pragma unroll
    for (int i = 0; i < 4; i++)
#pragma unroll
        for (int j = 0; j < 4; j++)
            g_G[((size_t)bc * CHUNK + q0 + ty * 4 + i) * CHUNK + k0 + tx * 4 + j] = acc[i][j];
}

// =====================================================================
// states: per-chunk B^T (decay * x*dt)   [256-thread proven version]
// =====================================================================
__global__ __launch_bounds__(256) void compute_states() {
    const int bx = blockIdx.x;
    const int h  = bx & 31;
    const int c  = (bx >> 5) & 7;
    const int b  = bx >> 8;
    const int bl0 = b * SEQLEN + c * CHUNK;

    float* Acs_s = smem_dyn;
    float* dt_s  = smem_dyn + 256;
    float* Bs    = smem_dyn + 512;
    float* Xs    = Bs + 64 * 65;

    const int tid = threadIdx.x;
    Acs_s[tid] = g_Acs[(size_t)bx * CHUNK + tid];
    dt_s[tid]  = g_dt[(size_t)(bl0 + tid) * NHEADS + h];
    __syncthreads();
    const float Alast = Acs_s[255];

    const int tx = tid & 15, ty = tid >> 4;
    float acc[4][8];
#pragma unroll
    for (int i = 0; i < 4; i++)
#pragma unroll
        for (int j = 0; j < 8; j++) acc[i][j] = 0.f;

    for (int kt = 0; kt < 4; kt++) {
        const int k0 = kt * 64;
        __syncthreads();
#pragma unroll
        for (int r = 0; r < 16; r++) {
            int idx = tid + r * 256;
            int kk = idx >> 6, n = idx & 63;
            float dec = __expf(Alast - Acs_s[k0 + kk]);
            Bs[kk * 65 + n] = g_xc[(size_t)(bl0 + k0 + kk) * CONVDIM + DINNER + n] * dec;
        }
#pragma unroll
        for (int r = 0; r < 8; r++) {
            int f4 = tid + r * 256;
            int kk = f4 >> 5, p4 = f4 & 31;
            float4 v = *(const float4*)(g_xc + (size_t)(bl0 + k0 + kk) * CONVDIM + h * HEADDIM + p4 * 4);
            float d = dt_s[k0 + kk];
            v.x *= d; v.y *= d; v.z *= d; v.w *= d;
            *(float4*)(Xs + kk * 128 + p4 * 4) = v;
        }
        __syncthreads();
        for (int kk = 0; kk < 64; kk++) {
            float a[4], bb[8];
#pragma unroll
            for (int i = 0; i < 4; i++) a[i] = Bs[kk * 65 + ty * 4 + i];
            *(float4*)&bb[0] = *(const float4*)(Xs + kk * 128 + tx * 8);
            *(float4*)&bb[4] = *(const float4*)(Xs + kk * 128 + tx * 8 + 4);
#pragma unroll
            for (int i = 0; i < 4; i++)
#pragma unroll
                for (int j = 0; j < 8; j++) acc[i][j] = fmaf(a[i], bb[j], acc[i][j]);
        }
    }

    size_t base = (size_t)bx * (DSTATE * HEADDIM);
#pragma unroll
    for (int i = 0; i < 4; i++) {
        int n = ty * 4 + i;
#pragma unroll
        for (int j = 0; j < 8; j += 4) {
            float4 v = make_float4(acc[i][j], acc[i][j + 1], acc[i][j + 2], acc[i][j + 3]);
            *(float4*)(g_states + base + (size_t)n * 128 + tx * 8 + j) = v;
        }
    }
}

// =====================================================================
// inter-chunk scan
// =====================================================================
__global__ __launch_bounds__(256) void chunk_scan() {
    const int bh = blockIdx.x;
    const int b = bh >> 5, h = bh & 31;
    __shared__ float cd[NCHUNK];
    if (threadIdx.x < NCHUNK) {
        int c = threadIdx.x;
        cd[c] = __expf(g_Acs[(size_t)(((b * 8 + c) * 32) + h) * CHUNK + 255]);
    }
    __syncthreads();
    for (int e = threadIdx.x; e < DSTATE * HEADDIM; e += 256) {
        float carry = 0.f;
#pragma unroll
        for (int c = 0; c < NCHUNK; c++) {
            size_t idx = (size_t)(((b * 8 + c) * 32) + h) * (DSTATE * HEADDIM) + e;
            g_prev[idx] = carry;
            carry = carry * cd[c] + g_states[idx];
        }
    }
}

// =====================================================================
// compute_Y on tensor cores: Y = (G∘L)@Xd + Ce@prev + x*D.
// CTA = 128 q-rows x 128 p of one (b,chunk,head). W/X tiles computed in
// fp32, split into bf16 hi/lo smem tiles, consumed by mma with the
// 3-term scheme (Wh·Xh + Wh·Xl + Wl·Xh).  4 warps (64x64 each).
// =====================================================================
#define YST 72
#define Y_SMEM (2048 + 4 * 128 * YST * 2)    // 75776 bytes

__global__ __launch_bounds__(128, 2) void compute_Y_mma(const float* __restrict__ Dp) {
    const int bx2 = blockIdx.x;
    const int qb  = bx2 & 1;
    const int bx  = bx2 >> 1;              // (b*8+c)*32 + h
    const int h   = bx & 31;
    const int bc  = bx >> 5;
    const int c   = bc & 7;
    const int b   = bc >> 3;
    const int bl0 = b * SEQLEN + c * CHUNK;
    const int q0  = qb * 128;

    float* Acs_s = smem_dyn;               // 256 floats
    float* dt_s  = smem_dyn + 256;         // 256 floats
    __nv_bfloat16* Wh  = (__nv_bfloat16*)(smem_dyn + 512);
    __nv_bfloat16* Wl  = Wh  + 128 * YST;
    __nv_bfloat16* XTh = Wl  + 128 * YST;
    __nv_bfloat16* XTl = XTh + 128 * YST;

    const int tid  = threadIdx.x;
    const int lane = tid & 31;
    const int wid  = tid >> 5;

    Acs_s[tid]       = g_Acs[(size_t)bx * CHUNK + tid];
    Acs_s[tid + 128] = g_Acs[(size_t)bx * CHUNK + tid + 128];
    dt_s[tid]        = g_dt[(size_t)(bl0 + tid) * NHEADS + h];
    dt_s[tid + 128]  = g_dt[(size_t)(bl0 + tid + 128) * NHEADS + h];

    const uint32_t whA = cvta_s(Wh);
    const uint32_t wlA = cvta_s(Wl);
    const uint32_t xhA = cvta_s(XTh);
    const uint32_t xlA = cvta_s(XTl);

    const int g2 = lane >> 2;
    const int t2 = (lane & 3) * 2;
    const int wr0 = (wid & 1) * 64;        // 2 warp-rows of 64 (q)
    const int wc0 = (wid >> 1) * 64;       // 2 warp-cols of 64 (p)
    const int aRow = ((lane >> 3) & 1) * 8 + (lane & 7);
    const int aK   = (lane >> 4) * 8;
    const int bRow = (lane >> 4) * 8 + (lane & 7);
    const int bK   = ((lane >> 3) & 1) * 8;

    float acc[4][8][4];
#pragma unroll
    for (int mt = 0; mt < 4; mt++)
#pragma unroll
        for (int nt = 0; nt < 8; nt++)
#pragma unroll
            for (int e = 0; e < 4; e++) acc[mt][nt][e] = 0.f;

    uint32_t ah[4][4], al[4][4], bh[4][4], blf[4][4];

    // ---- mma over one K=64 tile pair (Wh/Wl x XTh/XTl), 3 combos ----
    auto mma_tile = [&]() {
#pragma unroll
        for (int kg = 0; kg < 4; kg++) {
            const int kb = kg * 16;
#pragma unroll
            for (int mt = 0; mt < 4; mt++) {
                uint32_t off = ((wr0 + mt * 16 + aRow) * YST + kb + aK) * 2;
                ldsm_x4(ah[mt], whA + off);
                ldsm_x4(al[mt], wlA + off);
            }
#pragma unroll
            for (int p = 0; p < 4; p++) {
                uint32_t off = ((wc0 + p * 16 + bRow) * YST + kb + bK) * 2;
                ldsm_x4(bh[p], xhA + off);
                ldsm_x4(blf[p], xlA + off);
            }
#pragma unroll
            for (int mt = 0; mt < 4; mt++)
#pragma unroll
                for (int nt = 0; nt < 8; nt++) {
                    mma16816(acc[mt][nt], ah[mt], &bh[nt >> 1][(nt & 1) * 2]);
                    mma16816(acc[mt][nt], ah[mt], &blf[nt >> 1][(nt & 1) * 2]);
                    mma16816(acc[mt][nt], al[mt], &bh[nt >> 1][(nt & 1) * 2]);
                }
        }
    };

    // ---- diagonal part: Y += (G*exp(Acs_q-Acs_k)) @ (x*dt) ----
    const int ktmax = 2 + qb * 2;
    for (int kt = 0; kt < ktmax; kt++) {
        const int k0 = kt * 64;
        __syncthreads();
        // W tile fill (128 q x 64 k), split to bf16 hi/lo
        if (kt >= 2 * qb) {   // guarded (tile touches the diagonal)
#pragma unroll
            for (int r = 0; r < 64; r++) {
                int idx = tid + r * 128;
                int qq = idx >> 6, kk = idx & 63;
                int q = q0 + qq, k = k0 + kk;
                float w = 0.f;
                if (k <= q)
                    w = g_G[((size_t)bc * CHUNK + q) * CHUNK + k]
                        * __expf(Acs_s[q] - Acs_s[k]);
                split2(w, Wh + qq * YST + kk, Wl + qq * YST + kk);
            }
        } else {              // fully below diagonal: unguarded
#pragma unroll
            for (int r = 0; r < 64; r++) {
                int idx = tid + r * 128;
                int qq = idx >> 6, kk = idx & 63;
                int q = q0 + qq, k = k0 + kk;
                float w = g_G[((size_t)bc * CHUNK + q) * CHUNK + k]
                          * __expf(Acs_s[q] - Acs_s[k]);
                split2(w, Wh + qq * YST + kk, Wl + qq * YST + kk);
            }
        }
        // X^T tile fill (128 p x 64 k): x*dt, transposed, split
#pragma unroll
        for (int r = 0; r < 16; r++) {
            int f4 = tid + r * 128;
            int kk = f4 >> 5, p4 = f4 & 31;
            float4 v = *(const float4*)(g_xc + (size_t)(bl0 + k0 + kk) * CONVDIM
                                        + h * HEADDIM + p4 * 4);
            float d = dt_s[k0 + kk];
            float vv[4] = {v.x * d, v.y * d, v.z * d, v.w * d};
#pragma unroll
            for (int e = 0; e < 4; e++)
                split2(vv[e], XTh + (p4 * 4 + e) * YST + kk, XTl + (p4 * 4 + e) * YST + kk);
        }
        __syncthreads();
        mma_tile();
    }

    // ---- off part: Y += (C*exp(Acs_q)) @ prev ----
    __syncthreads();
#pragma unroll
    for (int r = 0; r < 64; r++) {
        int idx = tid + r * 128;
        int qq = idx >> 6, n = idx & 63;
        float val = g_xc[(size_t)(bl0 + q0 + qq) * CONVDIM + DINNER + DSTATE + n]
                    * __expf(Acs_s[q0 + qq]);
        split2(val, Wh + qq * YST + n, Wl + qq * YST + n);
    }
#pragma unroll
    for (int r = 0; r < 16; r++) {
        int f4 = tid + r * 128;
        int n = f4 >> 5, p4 = f4 & 31;
        float4 v = *(const float4*)(g_prev + (size_t)bx * (DSTATE * HEADDIM)
                                    + (size_t)n * 128 + p4 * 4);
        float vv[4] = {v.x, v.y, v.z, v.w};
#pragma unroll
        for (int e = 0; e < 4; e++)
            split2(vv[e], XTh + (p4 * 4 + e) * YST + n, XTl + (p4 * 4 + e) * YST + n);
    }
    __syncthreads();
    mma_tile();

    // ---- epilogue: add x*D, store to g_y ----
    const float Dh = Dp[h];
#pragma unroll
    for (int mt = 0; mt < 4; mt++) {
        int qq = wr0 + mt * 16 + g2;
        size_t bl_a = (size_t)(bl0 + q0 + qq);
        size_t bl_b = bl_a + 8;
#pragma unroll
        for (int nt = 0; nt < 8; nt++) {
            int cc = wc0 + nt * 8 + t2;
            float2 xa = *(const float2*)(g_xc + bl_a * CONVDIM + h * HEADDIM + cc);
            float2 xb = *(const float2*)(g_xc + bl_b * CONVDIM + h * HEADDIM + cc);
            *(float2*)(g_y + bl_a * DINNER + h * HEADDIM + cc) =
                make_float2(acc[mt][nt][0] + xa.x * Dh, acc[mt][nt][1] + xa.y * Dh);
            *(float2*)(g_y + bl_b * DINNER + h * HEADDIM + cc) =
                make_float2(acc[mt][nt][2] + xb.x * Dh, acc[mt][nt][3] + xb.y * Dh);
        }
    }
}

// =====================================================================
// RMSNorm + SiLU gate + split3(mode 0), single pass over y (registers)
// =====================================================================
__global__ __launch_bounds__(256) void rmsnorm_gate_split() {
    const int bl = blockIdx.x;
    const float* y = g_y + (size_t)bl * DINNER;
    const float* z = g_proj + (size_t)bl * DINPROJ;
    const int t = threadIdx.x;

    float yy[16];
    const float4* y4 = (const float4*)(y + t * 16);
    *(float4*)&yy[0]  = y4[0];
    *(float4*)&yy[4]  = y4[1];
    *(float4*)&yy[8]  = y4[2];
    *(float4*)&yy[12] = y4[3];

    float ss = 0.f;
#pragma unroll
    for (int e = 0; e < 16; e++) ss += yy[e] * yy[e];

    __shared__ float red[256];
    red[t] = ss;
    __syncthreads();
    for (int s = 128; s > 0; s >>= 1) {
        if (t < s) red[t] += red[t + s];
        __syncthreads();
    }
    float r = rsqrtf(red[0] / (float)DINNER + EPSF);

#pragma unroll
    for (int gb = 0; gb < 2; gb++) {
        const int base = t * 16 + gb * 8;
        float4 z0 = *(const float4*)(z + base);
        float4 z1 = *(const float4*)(z + base + 4);
        float zz[8] = {z0.x, z0.y, z0.z, z0.w, z1.x, z1.y, z1.z, z1.w};
        float v[8];
#pragma unroll
        for (int e = 0; e < 8; e++)
            v[e] = yy[gb * 8 + e] * r * (zz[e] / (1.f + __expf(-zz[e])));
        unsigned short h[24];
#pragma unroll
        for (int e = 0; e < 8; e++) {
            __nv_bfloat16 hi = __float2bfloat16(v[e]);
            __nv_bfloat16 lo = __float2bfloat16(v[e] - __bfloat162float(hi));
            unsigned short hb = __bfloat16_as_ushort(hi);
            unsigned short lb = __bfloat16_as_ushort(lo);
            h[3 * e] = hb; h[3 * e + 1] = hb; h[3 * e + 2] = lb;
        }
        uint4 w0, w1, w2;
        w0.x = h[0]  | (uint32_t)h[1]  << 16; w0.y = h[2]  | (uint32_t)h[3]  << 16;
        w0.z = h[4]  | (uint32_t)h[5]  << 16; w0.w = h[6]  | (uint32_t)h[7]  << 16;
        w1.x = h[8]  | (uint32_t)h[9]  << 16; w1.y = h[10] | (uint32_t)h[11] << 16;
        w1.z = h[12] | (uint32_t)h[13] << 16; w1.w = h[14] | (uint32_t)h[15] << 16;
        w2.x = h[16] | (uint32_t)h[17] << 16; w2.y = h[18] | (uint32_t)h[19] << 16;
        w2.z = h[20] | (uint32_t)h[21] << 16; w2.w = h[22] | (uint32_t)h[23] << 16;
        uint4* d4 = (uint4*)((char*)g_g3 + ((size_t)bl * K3_OUT + 3 * (size_t)base) * 2);
        d4[0] = w0; d4[1] = w1; d4[2] = w2;
    }
}

// =====================================================================
// launch
// =====================================================================
extern "C" void kernel_launch(void* const* d_in, const int* in_sizes, int n_in,
                              void* d_out, int out_size) {
    const float* x       = (const float*)d_in[0];
    const float* W_in    = (const float*)d_in[1];
    const float* conv_w  = (const float*)d_in[2];
    const float* conv_b  = (const float*)d_in[3];
    const float* A_log   = (const float*)d_in[4];
    const float* dt_bias = (const float*)d_in[5];
    const float* Dp      = (const float*)d_in[6];
    const float* W_out   = (const float*)d_in[7];
    float* out = (float*)d_out;

    float *p_proj = nullptr;
    __nv_bfloat16 *p_x3, *p_w3, *p_g3, *p_wo3;
    cudaGetSymbolAddress((void**)&p_proj, g_proj);
    cudaGetSymbolAddress((void**)&p_x3, g_x3);
    cudaGetSymbolAddress((void**)&p_w3, g_w3);
    cudaGetSymbolAddress((void**)&p_g3, g_g3);
    cudaGetSymbolAddress((void**)&p_wo3, g_wo3);

    const int SMEM_DYN = (512 + 64 * 65 + 64 * 128) * 4;   // 51456
    cudaFuncSetAttribute((const void*)compute_states,
                         cudaFuncAttributeMaxDynamicSharedMemorySize, SMEM_DYN);
    cudaFuncSetAttribute((const void*)compute_Y_mma,
                         cudaFuncAttributeMaxDynamicSharedMemorySize, Y_SMEM);
    cudaFuncSetAttribute((const void*)gemm_mma,
                         cudaFuncAttributeMaxDynamicSharedMemorySize, GEMM_SMEM);

    // --- split operands for GEMM1 ---
    split3<<<(unsigned)(((size_t)BL * DMODEL / 8 + 255) / 256), 256>>>(x, p_x3, (size_t)BL * DMODEL / 8, 0);
    {
        size_t halfRows = DINPROJ / 2;                       // 4176
        size_t n8 = halfRows * DMODEL / 8;
        split3<<<(unsigned)((n8 + 255) / 256), 256>>>(W_in, p_w3, n8, 1);
        split3<<<(unsigned)((n8 + 255) / 256), 256>>>(W_in + halfRows * DMODEL,
                                                      p_w3 + halfRows * K3_IN, n8, 1);
    }

    // --- GEMM1 (tensor cores): proj[:, :8320] = x @ W_in^T (dt cols skipped) ---
    {
        int tilesN = NPROJ_TC / 128;          // 65
        int tilesM = BL / 128;                // 64
        gemm_mma<<<tilesM * tilesN, 128, GEMM_SMEM>>>(
            p_x3, p_w3, p_proj, BL, NPROJ_TC, K3_IN, tilesN, DINPROJ);
    }

    // --- dt repair GEMM (exact fp32, split-K x 8) ---
    gemm_dt<<<dim3(BL / 32, 8), 256>>>(x, W_in + (size_t)(DINNER + CONVDIM) * DMODEL);

    // --- conv + silu (tiled, read-once) ---
    conv_silu_tiled<<<dim3(BATCH * (SEQLEN / 64), CONVDIM / 128), 256>>>(conv_w, conv_b);

    // --- dt, cumsum(dA) ---
    dt_scan<<<BATCH * NCHUNK * NHEADS, 256>>>(A_log, dt_bias);

    // --- SSD ---
    compute_G<<<dim3(BATCH * NCHUNK, 10), 256>>>();
    compute_states<<<BATCH * NCHUNK * NHEADS, 256, SMEM_DYN>>>();
    chunk_scan<<<BATCH * NHEADS, 256>>>();
    compute_Y_mma<<<BATCH * NCHUNK * NHEADS * 2, 128, Y_SMEM>>>(Dp);

    // --- rmsnorm + gate + split (fused, single-pass) ---
    rmsnorm_gate_split<<<BL, 256>>>();

    // --- split weights for GEMM2 ---
    split3<<<(unsigned)(((size_t)DMODEL * DINNER / 8 + 255) / 256), 256>>>(W_out, p_wo3, (size_t)DMODEL * DINNER / 8, 1);

    // --- GEMM2 (tensor cores): out = gated @ W_out^T ---
    {
        int tilesN = DMODEL / 128;            // 16
        int tilesM = BL / 128;                // 64
        gemm_mma<<<tilesM * tilesN, 128, GEMM_SMEM>>>(
            p_g3, p_wo3, out, BL, DMODEL, K3_OUT, tilesN, DMODEL);
    }
}